// round 3
// baseline (speedup 1.0000x reference)
#include <cuda_runtime.h>
#include <cuda_bf16.h>
#include <math.h>
#include <stdint.h>

#define D_    1024
#define DEPTH 8
#define H_    16
#define DH_   64
#define INNER 1024
#define NQ_   8
#define ED_   768
#define FF_   4096
#define TD_   320
#define BS_   32
#define N1_   1024
#define SCALE_ 0.125f

#define ACT_NONE 0
#define ACT_SILU 1
#define ACT_GELU 2

// ---------------- static scratch ----------------
__device__ float g_xp   [BS_*N1_*D_];
__device__ float g_xnorm[BS_*N1_*D_];
__device__ float g_temb0[BS_*TD_];
__device__ float g_temb1[BS_*D_];
__device__ float g_temb [BS_*D_];
__device__ float g_stemb[BS_*D_];
__device__ float g_ada  [BS_*4*D_];
__device__ float g_lat  [BS_*NQ_*D_];
__device__ float g_latn [BS_*NQ_*D_];
__device__ float g_q    [BS_*NQ_*D_];
__device__ float g_qp   [BS_*NQ_*H_*D_];
__device__ float g_att  [BS_*NQ_*H_*N1_];
__device__ float g_ov   [BS_*NQ_*H_*D_];
__device__ float g_vout [BS_*NQ_*D_];
__device__ float g_hff  [BS_*NQ_*D_];
__device__ float g_h1   [BS_*NQ_*FF_];

// ---------------- helpers ----------------
__device__ __forceinline__ void split2(float v, unsigned short& h, unsigned short& l)
{
    __nv_bfloat16 bh = __float2bfloat16_rn(v);
    float r = v - __bfloat162float(bh);
    __nv_bfloat16 bl = __float2bfloat16_rn(r);
    h = *reinterpret_cast<unsigned short*>(&bh);
    l = *reinterpret_cast<unsigned short*>(&bl);
}
__device__ __forceinline__ unsigned ld_u32(const unsigned short* p)
{
    return *reinterpret_cast<const unsigned*>(p);
}

// ---------------- tensor-core GEMM via split-bf16 mma.sync -----------------------
// C[M,N] = act(alpha * A@B (+bias)) (+C).  A row-major [M,K].
// BT=false: B row-major [K,N]; BT=true: B row-major [N,K] (used as B^T).
// ASCALE: A value scaled by ascale[k] (per-K) before use.
// BM=BN=128, BK=16, 256 threads (8 warps as 2x4, warp tile 64x32).
template<int ACT, bool ADD_C, bool ASCALE, bool BT>
__global__ void __launch_bounds__(256) tgemm_k(
    int M, int N, int K,
    const float* __restrict__ A, int lda, long sA,
    const float* __restrict__ B, int ldb, long sB,
    float* __restrict__ C, int ldc, long sC,
    const float* __restrict__ bias,
    const float* __restrict__ ascale,
    float alpha)
{
    __shared__ unsigned short sAh[128][24], sAl[128][24];
    __shared__ unsigned short sBh[128][24], sBl[128][24];

    A += (long)blockIdx.z * sA;
    B += (long)blockIdx.z * sB;
    C += (long)blockIdx.z * sC;
    const int bm = blockIdx.y * 128;
    const int bn = blockIdx.x * 128;
    const int t    = threadIdx.x;
    const int lane = t & 31, wid = t >> 5;
    const int g  = lane >> 2, tg = lane & 3;
    const int mw = (wid >> 2) * 64, nw = (wid & 3) * 32;

    float acc[4][4][4];
#pragma unroll
    for (int a = 0; a < 4; a++)
#pragma unroll
        for (int b = 0; b < 4; b++)
#pragma unroll
            for (int c = 0; c < 4; c++) acc[a][b][c] = 0.f;

    for (int k0 = 0; k0 < K; k0 += 16) {
        // ---- load A tile (128 x 16) ----
#pragma unroll
        for (int i = 0; i < 2; i++) {
            int f = t + i * 256;            // 0..511
            int row = f >> 2, kq = (f & 3) * 4;
            int gr = bm + row;
            float4 v = make_float4(0.f, 0.f, 0.f, 0.f);
            if (gr < M) v = *reinterpret_cast<const float4*>(A + (long)gr * lda + k0 + kq);
            if (ASCALE) {
                v.x *= ascale[k0 + kq];     v.y *= ascale[k0 + kq + 1];
                v.z *= ascale[k0 + kq + 2]; v.w *= ascale[k0 + kq + 3];
            }
            split2(v.x, sAh[row][kq],     sAl[row][kq]);
            split2(v.y, sAh[row][kq + 1], sAl[row][kq + 1]);
            split2(v.z, sAh[row][kq + 2], sAl[row][kq + 2]);
            split2(v.w, sAh[row][kq + 3], sAl[row][kq + 3]);
        }
        // ---- load B tile -> sB[n][k] ----
#pragma unroll
        for (int i = 0; i < 2; i++) {
            int f = t + i * 256;
            if (BT) {
                int row = f >> 2, kq = (f & 3) * 4;   // row = n
                int gc = bn + row;
                float4 v = make_float4(0.f, 0.f, 0.f, 0.f);
                if (gc < N) v = *reinterpret_cast<const float4*>(B + (long)gc * ldb + k0 + kq);
                split2(v.x, sBh[row][kq],     sBl[row][kq]);
                split2(v.y, sBh[row][kq + 1], sBl[row][kq + 1]);
                split2(v.z, sBh[row][kq + 2], sBl[row][kq + 2]);
                split2(v.w, sBh[row][kq + 3], sBl[row][kq + 3]);
            } else {
                int krow = f >> 5, nq = (f & 31) * 4;
                int gc = bn + nq;
                float4 v = make_float4(0.f, 0.f, 0.f, 0.f);
                if (gc < N) v = *reinterpret_cast<const float4*>(B + (long)(k0 + krow) * ldb + gc);
                unsigned short h, l;
                split2(v.x, h, l); sBh[nq][krow] = h;     sBl[nq][krow] = l;
                split2(v.y, h, l); sBh[nq + 1][krow] = h; sBl[nq + 1][krow] = l;
                split2(v.z, h, l); sBh[nq + 2][krow] = h; sBl[nq + 2][krow] = l;
                split2(v.w, h, l); sBh[nq + 3][krow] = h; sBl[nq + 3][krow] = l;
            }
        }
        __syncthreads();

        // ---- 3 passes: Ah*Bh, Ah*Bl, Al*Bh ----
#pragma unroll
        for (int p = 0; p < 3; p++) {
            const unsigned short (*Asel)[24] = (p == 2) ? sAl : sAh;
            const unsigned short (*Bsel)[24] = (p == 1) ? sBl : sBh;
            unsigned af[4][4], bf[4][2];
#pragma unroll
            for (int mt = 0; mt < 4; mt++) {
                int r = mw + mt * 16 + g;
                af[mt][0] = ld_u32(&Asel[r][tg * 2]);
                af[mt][1] = ld_u32(&Asel[r + 8][tg * 2]);
                af[mt][2] = ld_u32(&Asel[r][tg * 2 + 8]);
                af[mt][3] = ld_u32(&Asel[r + 8][tg * 2 + 8]);
            }
#pragma unroll
            for (int nt = 0; nt < 4; nt++) {
                int c = nw + nt * 8 + g;
                bf[nt][0] = ld_u32(&Bsel[c][tg * 2]);
                bf[nt][1] = ld_u32(&Bsel[c][tg * 2 + 8]);
            }
#pragma unroll
            for (int mt = 0; mt < 4; mt++)
#pragma unroll
                for (int nt = 0; nt < 4; nt++) {
                    asm volatile(
                        "mma.sync.aligned.m16n8k16.row.col.f32.bf16.bf16.f32 "
                        "{%0,%1,%2,%3},{%4,%5,%6,%7},{%8,%9},{%0,%1,%2,%3};\n"
                        : "+f"(acc[mt][nt][0]), "+f"(acc[mt][nt][1]),
                          "+f"(acc[mt][nt][2]), "+f"(acc[mt][nt][3])
                        : "r"(af[mt][0]), "r"(af[mt][1]), "r"(af[mt][2]), "r"(af[mt][3]),
                          "r"(bf[nt][0]), "r"(bf[nt][1]));
                }
        }
        __syncthreads();
    }

    // ---- epilogue ----
#pragma unroll
    for (int mt = 0; mt < 4; mt++) {
#pragma unroll
        for (int nt = 0; nt < 4; nt++) {
            int gc = bn + nw + nt * 8 + tg * 2;
            if (gc >= N) continue;
#pragma unroll
            for (int rr = 0; rr < 2; rr++) {
                int gr = bm + mw + mt * 16 + g + rr * 8;
                if (gr >= M) continue;
                float f0 = acc[mt][nt][rr * 2]     * alpha;
                float f1 = acc[mt][nt][rr * 2 + 1] * alpha;
                if (bias) { f0 += bias[gc]; f1 += bias[gc + 1]; }
                if (ACT == ACT_SILU) {
                    f0 = f0 / (1.f + expf(-f0));
                    f1 = f1 / (1.f + expf(-f1));
                }
                if (ACT == ACT_GELU) {
                    f0 = 0.5f * f0 * (1.f + erff(f0 * 0.70710678118654752f));
                    f1 = 0.5f * f1 * (1.f + erff(f1 * 0.70710678118654752f));
                }
                long off = (long)gr * ldc + gc;
                if (ADD_C) { f0 += C[off]; f1 += C[off + 1]; }
                C[off] = f0; C[off + 1] = f1;
            }
        }
    }
}

// ---------------- LayerNorm over fixed D=1024, block=256 -------------------------
template<bool AFFINE>
__global__ void __launch_bounds__(256) ln_k(const float* __restrict__ x, float* __restrict__ y,
                                            const float* __restrict__ g, const float* __restrict__ b)
{
    const long row = blockIdx.x;
    const float* xr = x + row * D_;
    const int t = threadIdx.x;
    float vals[4];
    float s = 0.f;
#pragma unroll
    for (int i = 0; i < 4; i++) { vals[i] = xr[t + i * 256]; s += vals[i]; }
    __shared__ float red[256];
    red[t] = s; __syncthreads();
    for (int off = 128; off > 0; off >>= 1) { if (t < off) red[t] += red[t + off]; __syncthreads(); }
    float m = red[0] * (1.f / D_);
    __syncthreads();
    float vs = 0.f;
#pragma unroll
    for (int i = 0; i < 4; i++) { float d = vals[i] - m; vs += d * d; }
    red[t] = vs; __syncthreads();
    for (int off = 128; off > 0; off >>= 1) { if (t < off) red[t] += red[t + off]; __syncthreads(); }
    float var = red[0] * (1.f / D_);
    float rs = 1.f / sqrtf(var + 1e-5f);
#pragma unroll
    for (int i = 0; i < 4; i++) {
        int c = t + i * 256;
        float o = (vals[i] - m) * rs;
        if (AFFINE) o = o * g[c] + b[c];
        y[row * D_ + c] = o;
    }
}

// ---------------- softmax over fixed 1024 cols -----------------------------------
__global__ void __launch_bounds__(256) softmax_k(float* __restrict__ x)
{
    const long row = blockIdx.x;
    float* p = x + row * N1_;
    const int t = threadIdx.x;
    float v[4]; float mx = -1e30f;
#pragma unroll
    for (int i = 0; i < 4; i++) { v[i] = p[t + i * 256]; mx = fmaxf(mx, v[i]); }
    __shared__ float red[256];
    red[t] = mx; __syncthreads();
    for (int off = 128; off > 0; off >>= 1) { if (t < off) red[t] = fmaxf(red[t], red[t + off]); __syncthreads(); }
    mx = red[0]; __syncthreads();
    float s = 0.f;
#pragma unroll
    for (int i = 0; i < 4; i++) { v[i] = expf(v[i] - mx); s += v[i]; }
    red[t] = s; __syncthreads();
    for (int off = 128; off > 0; off >>= 1) { if (t < off) red[t] += red[t + off]; __syncthreads(); }
    float inv = 1.f / red[0];
#pragma unroll
    for (int i = 0; i < 4; i++) p[t + i * 256] = v[i] * inv;
}

// ---------------- small elementwise kernels --------------------------------------
__global__ void timestep_k(const float* __restrict__ ts, float* __restrict__ out)
{
    int b = blockIdx.x, i = threadIdx.x;
    int j = (i < 160) ? i : (i - 160);
    float f = expf(-logf(10000.f) * (float)j / 160.f);
    float af = ts[b] * f;
    double a = (double)af;
    out[b * TD_ + i] = (i < 160) ? (float)cos(a) : (float)sin(a);
}

__global__ void silu_k(const float* __restrict__ x, float* __restrict__ y, int n)
{
    int i = blockIdx.x * blockDim.x + threadIdx.x;
    if (i < n) { float v = x[i]; y[i] = v / (1.f + expf(-v)); }
}

__global__ void bcast_lat_k(const float* __restrict__ src, float* __restrict__ dst, int n, int period)
{
    int i = blockIdx.x * blockDim.x + threadIdx.x;
    if (i < n) dst[i] = src[i % period];
}

__global__ void modulate_k(float* __restrict__ q, const float* __restrict__ ada)
{
    int idx = blockIdx.x * blockDim.x + threadIdx.x;
    if (idx >= BS_ * NQ_ * D_) return;
    int b = idx / (NQ_ * D_);
    int c = idx & (D_ - 1);
    float sc = ada[b * 4 * D_ + 2 * D_ + c];
    float sh = ada[b * 4 * D_ + c];
    q[idx] = q[idx] * (1.f + sc) + sh;
}

__global__ void ovmod_k(float* __restrict__ ov, const float* __restrict__ g1, const float* __restrict__ b1)
{
    int idx = blockIdx.x * blockDim.x + threadIdx.x;
    if (idx >= BS_ * NQ_ * H_ * D_) return;
    int d = idx & (D_ - 1);
    ov[idx] = g1[d] * ov[idx] + b1[d];
}

// ---------------- launch ----------------------------------------------------------
static inline dim3 tgrid(int M, int N, int b)
{
    return dim3((unsigned)((N + 127) / 128), (unsigned)((M + 127) / 128), (unsigned)b);
}

extern "C" void kernel_launch(void* const* d_in, const int* in_sizes, int n_in,
                              void* d_out, int out_size)
{
    const float* in_x   = (const float*)d_in[0];
    const float* in_ts  = (const float*)d_in[1];
    const float* in_lat = (const float*)d_in[2];
    const float* te_w1  = (const float*)d_in[3];
    const float* te_b1  = (const float*)d_in[4];
    const float* te_w2  = (const float*)d_in[5];
    const float* te_b2  = (const float*)d_in[6];
    const float* pin_w  = (const float*)d_in[7];
    const float* pin_b  = (const float*)d_in[8];
    const float* ln1_g  = (const float*)d_in[9];
    const float* ln1_b  = (const float*)d_in[10];
    const float* ln2_g  = (const float*)d_in[11];
    const float* ln2_b  = (const float*)d_in[12];
    const float* wq     = (const float*)d_in[13];
    const float* wkv    = (const float*)d_in[14];
    const float* wo     = (const float*)d_in[15];
    const float* flg    = (const float*)d_in[16];
    const float* flb    = (const float*)d_in[17];
    const float* fw1    = (const float*)d_in[18];
    const float* fw2    = (const float*)d_in[19];
    const float* aw     = (const float*)d_in[20];
    const float* ab     = (const float*)d_in[21];
    const float* pout_w = (const float*)d_in[22];
    const float* pout_b = (const float*)d_in[23];
    const float* ng     = (const float*)d_in[24];
    const float* nb     = (const float*)d_in[25];
    float* out = (float*)d_out;

    float *xp, *xnorm, *temb0, *temb1, *temb, *stemb, *ada, *lat, *latn, *q, *qp, *att, *ov, *vout, *hff, *h1;
    cudaGetSymbolAddress((void**)&xp,    g_xp);
    cudaGetSymbolAddress((void**)&xnorm, g_xnorm);
    cudaGetSymbolAddress((void**)&temb0, g_temb0);
    cudaGetSymbolAddress((void**)&temb1, g_temb1);
    cudaGetSymbolAddress((void**)&temb,  g_temb);
    cudaGetSymbolAddress((void**)&stemb, g_stemb);
    cudaGetSymbolAddress((void**)&ada,   g_ada);
    cudaGetSymbolAddress((void**)&lat,   g_lat);
    cudaGetSymbolAddress((void**)&latn,  g_latn);
    cudaGetSymbolAddress((void**)&q,     g_q);
    cudaGetSymbolAddress((void**)&qp,    g_qp);
    cudaGetSymbolAddress((void**)&att,   g_att);
    cudaGetSymbolAddress((void**)&ov,    g_ov);
    cudaGetSymbolAddress((void**)&vout,  g_vout);
    cudaGetSymbolAddress((void**)&hff,   g_hff);
    cudaGetSymbolAddress((void**)&h1,    g_h1);

    // --- timestep embedding ---
    timestep_k<<<BS_, TD_>>>(in_ts, temb0);
    tgemm_k<ACT_SILU,false,false,false><<<tgrid(BS_, D_, 1), 256>>>(
        BS_, D_, TD_, temb0, TD_, 0, te_w1, D_, 0, temb1, D_, 0, te_b1, nullptr, 1.f);
    tgemm_k<ACT_NONE,false,false,false><<<tgrid(BS_, D_, 1), 256>>>(
        BS_, D_, D_, temb1, D_, 0, te_w2, D_, 0, temb, D_, 0, te_b2, nullptr, 1.f);
    silu_k<<<(BS_*D_ + 255) / 256, 256>>>(temb, stemb, BS_ * D_);

    // --- proj_in + layer-invariant LN of xp (fp32 now; split handles precision) ---
    tgemm_k<ACT_NONE,false,false,false><<<tgrid(BS_*N1_, D_, 1), 256>>>(
        BS_*N1_, D_, ED_, in_x, ED_, 0, pin_w, D_, 0, xp, D_, 0, pin_b, nullptr, 1.f);
    ln_k<false><<<BS_*N1_, 256>>>(xp, xnorm, nullptr, nullptr);

    bcast_lat_k<<<(BS_*NQ_*D_ + 255) / 256, 256>>>(in_lat, lat, BS_*NQ_*D_, NQ_*D_);

    for (int l = 0; l < DEPTH; l++) {
        const float* wq_l  = wq  + (long)l * D_ * INNER;
        const float* wkv_l = wkv + (long)l * D_ * 2 * INNER;
        const float* wo_l  = wo  + (long)l * INNER * D_;
        const float* fw1_l = fw1 + (long)l * D_ * FF_;
        const float* fw2_l = fw2 + (long)l * FF_ * D_;
        const float* aw_l  = aw  + (long)l * D_ * 4 * D_;
        const float* ab_l  = ab  + (long)l * 4 * D_;
        const float* g1 = ln1_g + l * D_;
        const float* b1 = ln1_b + l * D_;
        const float* g2 = ln2_g + l * D_;
        const float* b2 = ln2_b + l * D_;
        const float* fg = flg + l * D_;
        const float* fb = flb + l * D_;

        // adaLN params
        tgemm_k<ACT_NONE,false,false,false><<<tgrid(BS_, 4*D_, 1), 256>>>(
            BS_, 4*D_, D_, stemb, D_, 0, aw_l, 4*D_, 0, ada, 4*D_, 0, ab_l, nullptr, 1.f);

        // latents LN + q projection + modulation
        ln_k<true><<<BS_*NQ_, 256>>>(lat, latn, g2, b2);
        tgemm_k<ACT_NONE,false,false,false><<<tgrid(BS_*NQ_, INNER, 1), 256>>>(
            BS_*NQ_, INNER, D_, latn, D_, 0, wq_l, INNER, 0, q, INNER, 0, nullptr, nullptr, 1.f);
        modulate_k<<<(BS_*NQ_*D_ + 255) / 256, 256>>>(q, ada);

        // qproj[b,q,h,d] = SCALE * qmod[b,q,h,:] @ wk_h^T   (batched over heads, BT)
        tgemm_k<ACT_NONE,false,false,true><<<tgrid(BS_*NQ_, D_, H_), 256>>>(
            BS_*NQ_, D_, DH_, q, INNER, 64, wkv_l, 2*INNER, 64,
            qp, H_*D_, (long)D_, nullptr, nullptr, SCALE_);

        // logits[b,(q,h),n] = (qproj .* g1) @ xnorm_b^T   (b1 drops: softmax shift-invariance)
        tgemm_k<ACT_NONE,false,true,true><<<tgrid(NQ_*H_, N1_, BS_), 256>>>(
            NQ_*H_, N1_, D_, qp, D_, (long)NQ_*H_*D_, xnorm, D_, (long)N1_*D_,
            att, N1_, (long)NQ_*H_*N1_, nullptr, g1, 1.f);

        softmax_k<<<BS_*NQ_*H_, 256>>>(att);

        // ov[b,(q,h),d] = attn @ xnorm_b
        tgemm_k<ACT_NONE,false,false,false><<<tgrid(NQ_*H_, D_, BS_), 256>>>(
            NQ_*H_, D_, N1_, att, N1_, (long)NQ_*H_*N1_, xnorm, D_, (long)N1_*D_,
            ov, D_, (long)NQ_*H_*D_, nullptr, nullptr, 1.f);

        // ov <- g1*ov + b1  (b1 survives: sum(attn)=1)
        ovmod_k<<<(BS_*NQ_*H_*D_ + 255) / 256, 256>>>(ov, g1, b1);

        // vout[b,q,h*64+dh] = ovm[b,q,h,:] @ wv_h   (batched over heads)
        tgemm_k<ACT_NONE,false,false,false><<<tgrid(BS_*NQ_, DH_, H_), 256>>>(
            BS_*NQ_, DH_, D_, ov, H_*D_, (long)D_, wkv_l + INNER, 2*INNER, 64,
            vout, D_, 64, nullptr, nullptr, 1.f);

        // lat += vout @ wo
        tgemm_k<ACT_NONE,true,false,false><<<tgrid(BS_*NQ_, D_, 1), 256>>>(
            BS_*NQ_, D_, INNER, vout, INNER, 0, wo_l, D_, 0, lat, D_, 0, nullptr, nullptr, 1.f);

        // FF block
        ln_k<true><<<BS_*NQ_, 256>>>(lat, hff, fg, fb);
        tgemm_k<ACT_GELU,false,false,false><<<tgrid(BS_*NQ_, FF_, 1), 256>>>(
            BS_*NQ_, FF_, D_, hff, D_, 0, fw1_l, FF_, 0, h1, FF_, 0, nullptr, nullptr, 1.f);
        tgemm_k<ACT_NONE,true,false,false><<<tgrid(BS_*NQ_, D_, 1), 256>>>(
            BS_*NQ_, D_, FF_, h1, FF_, 0, fw2_l, D_, 0, lat, D_, 0, nullptr, nullptr, 1.f);
    }

    // --- proj_out + final LN ---
    tgemm_k<ACT_NONE,false,false,false><<<tgrid(BS_*NQ_, D_, 1), 256>>>(
        BS_*NQ_, D_, D_, lat, D_, 0, pout_w, D_, 0, hff, D_, 0, pout_b, nullptr, 1.f);
    ln_k<true><<<BS_*NQ_, 256>>>(hff, out, ng, nb);
}

// round 4
// speedup vs baseline: 1.0150x; 1.0150x over previous
#include <cuda_runtime.h>
#include <cuda_bf16.h>
#include <math.h>
#include <stdint.h>

#define D_    1024
#define DEPTH 8
#define H_    16
#define DH_   64
#define INNER 1024
#define NQ_   8
#define ED_   768
#define FF_   4096
#define TD_   320
#define BS_   32
#define N1_   1024
#define SCALE_ 0.125f

#define ACT_NONE 0
#define ACT_SILU 1
#define ACT_GELU 2

// ---------------- static scratch ----------------
__device__ float g_xp   [BS_*N1_*D_];
__device__ float g_xnorm[BS_*N1_*D_];
__device__ float g_temb0[BS_*TD_];
__device__ float g_temb1[BS_*D_];
__device__ float g_temb [BS_*D_];
__device__ float g_stemb[BS_*D_];
__device__ float g_ada  [BS_*4*D_];
__device__ float g_lat  [BS_*NQ_*D_];
__device__ float g_latn [BS_*NQ_*D_];
__device__ float g_q    [BS_*NQ_*D_];
__device__ float g_qp   [BS_*NQ_*H_*D_];
__device__ float g_att  [BS_*NQ_*H_*N1_];
__device__ float g_ov   [BS_*NQ_*H_*D_];
__device__ float g_vout [BS_*NQ_*D_];
__device__ float g_hff  [BS_*NQ_*D_];
__device__ float g_h1   [BS_*NQ_*FF_];

// ---------------- helpers ----------------
__device__ __forceinline__ void split2(float v, unsigned short& h, unsigned short& l)
{
    __nv_bfloat16 bh = __float2bfloat16_rn(v);
    float r = v - __bfloat162float(bh);
    __nv_bfloat16 bl = __float2bfloat16_rn(r);
    h = *reinterpret_cast<unsigned short*>(&bh);
    l = *reinterpret_cast<unsigned short*>(&bl);
}
__device__ __forceinline__ unsigned ld_u32(const unsigned short* p)
{
    return *reinterpret_cast<const unsigned*>(p);
}

// ---------------- tensor-core GEMM via split-bf16 mma.sync -----------------------
// C[M,N] = act(alpha * A@B (+bias)) (+C).  A row-major [M,K].
// BT=false: B row-major [K,N]; BT=true: B row-major [N,K] (used as B^T).
// ASCALE: A value scaled by ascale[k] (per-K) before use.
// BM=BN=128, BK=16, 256 threads (8 warps as 2x4, warp tile 64x32).
template<int ACT, bool ADD_C, bool ASCALE, bool BT>
__global__ void __launch_bounds__(256) tgemm_k(
    int M, int N, int K,
    const float* __restrict__ A, int lda, long sA,
    const float* __restrict__ B, int ldb, long sB,
    float* __restrict__ C, int ldc, long sC,
    const float* __restrict__ bias,
    const float* __restrict__ ascale,
    float alpha)
{
    __shared__ unsigned short sAh[128][24], sAl[128][24];
    __shared__ unsigned short sBh[128][24], sBl[128][24];

    A += (long)blockIdx.z * sA;
    B += (long)blockIdx.z * sB;
    C += (long)blockIdx.z * sC;
    const int bm = blockIdx.y * 128;
    const int bn = blockIdx.x * 128;
    const int t    = threadIdx.x;
    const int lane = t & 31, wid = t >> 5;
    const int g  = lane >> 2, tg = lane & 3;
    const int mw = (wid >> 2) * 64, nw = (wid & 3) * 32;

    float acc[4][4][4];
#pragma unroll
    for (int a = 0; a < 4; a++)
#pragma unroll
        for (int b = 0; b < 4; b++)
#pragma unroll
            for (int c = 0; c < 4; c++) acc[a][b][c] = 0.f;

    for (int k0 = 0; k0 < K; k0 += 16) {
        // ---- load A tile (128 x 16) ----
#pragma unroll
        for (int i = 0; i < 2; i++) {
            int f = t + i * 256;            // 0..511
            int row = f >> 2, kq = (f & 3) * 4;
            int gr = bm + row;
            float4 v = make_float4(0.f, 0.f, 0.f, 0.f);
            if (gr < M) v = *reinterpret_cast<const float4*>(A + (long)gr * lda + k0 + kq);
            if (ASCALE) {
                v.x *= ascale[k0 + kq];     v.y *= ascale[k0 + kq + 1];
                v.z *= ascale[k0 + kq + 2]; v.w *= ascale[k0 + kq + 3];
            }
            split2(v.x, sAh[row][kq],     sAl[row][kq]);
            split2(v.y, sAh[row][kq + 1], sAl[row][kq + 1]);
            split2(v.z, sAh[row][kq + 2], sAl[row][kq + 2]);
            split2(v.w, sAh[row][kq + 3], sAl[row][kq + 3]);
        }
        // ---- load B tile -> sB[n][k] ----
#pragma unroll
        for (int i = 0; i < 2; i++) {
            int f = t + i * 256;
            if (BT) {
                int row = f >> 2, kq = (f & 3) * 4;   // row = n
                int gc = bn + row;
                float4 v = make_float4(0.f, 0.f, 0.f, 0.f);
                if (gc < N) v = *reinterpret_cast<const float4*>(B + (long)gc * ldb + k0 + kq);
                split2(v.x, sBh[row][kq],     sBl[row][kq]);
                split2(v.y, sBh[row][kq + 1], sBl[row][kq + 1]);
                split2(v.z, sBh[row][kq + 2], sBl[row][kq + 2]);
                split2(v.w, sBh[row][kq + 3], sBl[row][kq + 3]);
            } else {
                int krow = f >> 5, nq = (f & 31) * 4;
                int gc = bn + nq;
                float4 v = make_float4(0.f, 0.f, 0.f, 0.f);
                if (gc < N) v = *reinterpret_cast<const float4*>(B + (long)(k0 + krow) * ldb + gc);
                unsigned short h, l;
                split2(v.x, h, l); sBh[nq][krow] = h;     sBl[nq][krow] = l;
                split2(v.y, h, l); sBh[nq + 1][krow] = h; sBl[nq + 1][krow] = l;
                split2(v.z, h, l); sBh[nq + 2][krow] = h; sBl[nq + 2][krow] = l;
                split2(v.w, h, l); sBh[nq + 3][krow] = h; sBl[nq + 3][krow] = l;
            }
        }
        __syncthreads();

        // ---- 3 passes: Ah*Bh, Ah*Bl, Al*Bh ----
#pragma unroll
        for (int p = 0; p < 3; p++) {
            const unsigned short (*Asel)[24] = (p == 2) ? sAl : sAh;
            const unsigned short (*Bsel)[24] = (p == 1) ? sBl : sBh;
            unsigned af[4][4], bf[4][2];
#pragma unroll
            for (int mt = 0; mt < 4; mt++) {
                int r = mw + mt * 16 + g;
                af[mt][0] = ld_u32(&Asel[r][tg * 2]);
                af[mt][1] = ld_u32(&Asel[r + 8][tg * 2]);
                af[mt][2] = ld_u32(&Asel[r][tg * 2 + 8]);
                af[mt][3] = ld_u32(&Asel[r + 8][tg * 2 + 8]);
            }
#pragma unroll
            for (int nt = 0; nt < 4; nt++) {
                int c = nw + nt * 8 + g;
                bf[nt][0] = ld_u32(&Bsel[c][tg * 2]);
                bf[nt][1] = ld_u32(&Bsel[c][tg * 2 + 8]);
            }
#pragma unroll
            for (int mt = 0; mt < 4; mt++)
#pragma unroll
                for (int nt = 0; nt < 4; nt++) {
                    asm volatile(
                        "mma.sync.aligned.m16n8k16.row.col.f32.bf16.bf16.f32 "
                        "{%0,%1,%2,%3},{%4,%5,%6,%7},{%8,%9},{%0,%1,%2,%3};\n"
                        : "+f"(acc[mt][nt][0]), "+f"(acc[mt][nt][1]),
                          "+f"(acc[mt][nt][2]), "+f"(acc[mt][nt][3])
                        : "r"(af[mt][0]), "r"(af[mt][1]), "r"(af[mt][2]), "r"(af[mt][3]),
                          "r"(bf[nt][0]), "r"(bf[nt][1]));
                }
        }
        __syncthreads();
    }

    // ---- epilogue ----
#pragma unroll
    for (int mt = 0; mt < 4; mt++) {
#pragma unroll
        for (int nt = 0; nt < 4; nt++) {
            int gc = bn + nw + nt * 8 + tg * 2;
            if (gc >= N) continue;
#pragma unroll
            for (int rr = 0; rr < 2; rr++) {
                int gr = bm + mw + mt * 16 + g + rr * 8;
                if (gr >= M) continue;
                float f0 = acc[mt][nt][rr * 2]     * alpha;
                float f1 = acc[mt][nt][rr * 2 + 1] * alpha;
                if (bias) { f0 += bias[gc]; f1 += bias[gc + 1]; }
                if (ACT == ACT_SILU) {
                    f0 = f0 / (1.f + expf(-f0));
                    f1 = f1 / (1.f + expf(-f1));
                }
                if (ACT == ACT_GELU) {
                    f0 = 0.5f * f0 * (1.f + erff(f0 * 0.70710678118654752f));
                    f1 = 0.5f * f1 * (1.f + erff(f1 * 0.70710678118654752f));
                }
                long off = (long)gr * ldc + gc;
                if (ADD_C) { f0 += C[off]; f1 += C[off + 1]; }
                C[off] = f0; C[off + 1] = f1;
            }
        }
    }
}

// ---------------- LayerNorm over fixed D=1024, block=256 -------------------------
template<bool AFFINE>
__global__ void __launch_bounds__(256) ln_k(const float* __restrict__ x, float* __restrict__ y,
                                            const float* __restrict__ g, const float* __restrict__ b)
{
    const long row = blockIdx.x;
    const float* xr = x + row * D_;
    const int t = threadIdx.x;
    float vals[4];
    float s = 0.f;
#pragma unroll
    for (int i = 0; i < 4; i++) { vals[i] = xr[t + i * 256]; s += vals[i]; }
    __shared__ float red[256];
    red[t] = s; __syncthreads();
    for (int off = 128; off > 0; off >>= 1) { if (t < off) red[t] += red[t + off]; __syncthreads(); }
    float m = red[0] * (1.f / D_);
    __syncthreads();
    float vs = 0.f;
#pragma unroll
    for (int i = 0; i < 4; i++) { float d = vals[i] - m; vs += d * d; }
    red[t] = vs; __syncthreads();
    for (int off = 128; off > 0; off >>= 1) { if (t < off) red[t] += red[t + off]; __syncthreads(); }
    float var = red[0] * (1.f / D_);
    float rs = 1.f / sqrtf(var + 1e-5f);
#pragma unroll
    for (int i = 0; i < 4; i++) {
        int c = t + i * 256;
        float o = (vals[i] - m) * rs;
        if (AFFINE) o = o * g[c] + b[c];
        y[row * D_ + c] = o;
    }
}

// ---------------- softmax over fixed 1024 cols -----------------------------------
__global__ void __launch_bounds__(256) softmax_k(float* __restrict__ x)
{
    const long row = blockIdx.x;
    float* p = x + row * N1_;
    const int t = threadIdx.x;
    float v[4]; float mx = -1e30f;
#pragma unroll
    for (int i = 0; i < 4; i++) { v[i] = p[t + i * 256]; mx = fmaxf(mx, v[i]); }
    __shared__ float red[256];
    red[t] = mx; __syncthreads();
    for (int off = 128; off > 0; off >>= 1) { if (t < off) red[t] = fmaxf(red[t], red[t + off]); __syncthreads(); }
    mx = red[0]; __syncthreads();
    float s = 0.f;
#pragma unroll
    for (int i = 0; i < 4; i++) { v[i] = expf(v[i] - mx); s += v[i]; }
    red[t] = s; __syncthreads();
    for (int off = 128; off > 0; off >>= 1) { if (t < off) red[t] += red[t + off]; __syncthreads(); }
    float inv = 1.f / red[0];
#pragma unroll
    for (int i = 0; i < 4; i++) p[t + i * 256] = v[i] * inv;
}

// ---------------- small elementwise kernels --------------------------------------
__global__ void timestep_k(const float* __restrict__ ts, float* __restrict__ out)
{
    int b = blockIdx.x, i = threadIdx.x;
    int j = (i < 160) ? i : (i - 160);
    float f = expf(-logf(10000.f) * (float)j / 160.f);
    float af = ts[b] * f;
    double a = (double)af;
    out[b * TD_ + i] = (i < 160) ? (float)cos(a) : (float)sin(a);
}

__global__ void silu_k(const float* __restrict__ x, float* __restrict__ y, int n)
{
    int i = blockIdx.x * blockDim.x + threadIdx.x;
    if (i < n) { float v = x[i]; y[i] = v / (1.f + expf(-v)); }
}

__global__ void bcast_lat_k(const float* __restrict__ src, float* __restrict__ dst, int n, int period)
{
    int i = blockIdx.x * blockDim.x + threadIdx.x;
    if (i < n) dst[i] = src[i % period];
}

__global__ void modulate_k(float* __restrict__ q, const float* __restrict__ ada)
{
    int idx = blockIdx.x * blockDim.x + threadIdx.x;
    if (idx >= BS_ * NQ_ * D_) return;
    int b = idx / (NQ_ * D_);
    int c = idx & (D_ - 1);
    float sc = ada[b * 4 * D_ + 2 * D_ + c];
    float sh = ada[b * 4 * D_ + c];
    q[idx] = q[idx] * (1.f + sc) + sh;
}

__global__ void ovmod_k(float* __restrict__ ov, const float* __restrict__ g1, const float* __restrict__ b1)
{
    int idx = blockIdx.x * blockDim.x + threadIdx.x;
    if (idx >= BS_ * NQ_ * H_ * D_) return;
    int d = idx & (D_ - 1);
    ov[idx] = g1[d] * ov[idx] + b1[d];
}

// ---------------- launch ----------------------------------------------------------
static inline dim3 tgrid(int M, int N, int b)
{
    return dim3((unsigned)((N + 127) / 128), (unsigned)((M + 127) / 128), (unsigned)b);
}

extern "C" void kernel_launch(void* const* d_in, const int* in_sizes, int n_in,
                              void* d_out, int out_size)
{
    const float* in_x   = (const float*)d_in[0];
    const float* in_ts  = (const float*)d_in[1];
    const float* in_lat = (const float*)d_in[2];
    const float* te_w1  = (const float*)d_in[3];
    const float* te_b1  = (const float*)d_in[4];
    const float* te_w2  = (const float*)d_in[5];
    const float* te_b2  = (const float*)d_in[6];
    const float* pin_w  = (const float*)d_in[7];
    const float* pin_b  = (const float*)d_in[8];
    const float* ln1_g  = (const float*)d_in[9];
    const float* ln1_b  = (const float*)d_in[10];
    const float* ln2_g  = (const float*)d_in[11];
    const float* ln2_b  = (const float*)d_in[12];
    const float* wq     = (const float*)d_in[13];
    const float* wkv    = (const float*)d_in[14];
    const float* wo     = (const float*)d_in[15];
    const float* flg    = (const float*)d_in[16];
    const float* flb    = (const float*)d_in[17];
    const float* fw1    = (const float*)d_in[18];
    const float* fw2    = (const float*)d_in[19];
    const float* aw     = (const float*)d_in[20];
    const float* ab     = (const float*)d_in[21];
    const float* pout_w = (const float*)d_in[22];
    const float* pout_b = (const float*)d_in[23];
    const float* ng     = (const float*)d_in[24];
    const float* nb     = (const float*)d_in[25];
    float* out = (float*)d_out;

    float *xp, *xnorm, *temb0, *temb1, *temb, *stemb, *ada, *lat, *latn, *q, *qp, *att, *ov, *vout, *hff, *h1;
    cudaGetSymbolAddress((void**)&xp,    g_xp);
    cudaGetSymbolAddress((void**)&xnorm, g_xnorm);
    cudaGetSymbolAddress((void**)&temb0, g_temb0);
    cudaGetSymbolAddress((void**)&temb1, g_temb1);
    cudaGetSymbolAddress((void**)&temb,  g_temb);
    cudaGetSymbolAddress((void**)&stemb, g_stemb);
    cudaGetSymbolAddress((void**)&ada,   g_ada);
    cudaGetSymbolAddress((void**)&lat,   g_lat);
    cudaGetSymbolAddress((void**)&latn,  g_latn);
    cudaGetSymbolAddress((void**)&q,     g_q);
    cudaGetSymbolAddress((void**)&qp,    g_qp);
    cudaGetSymbolAddress((void**)&att,   g_att);
    cudaGetSymbolAddress((void**)&ov,    g_ov);
    cudaGetSymbolAddress((void**)&vout,  g_vout);
    cudaGetSymbolAddress((void**)&hff,   g_hff);
    cudaGetSymbolAddress((void**)&h1,    g_h1);

    // --- timestep embedding ---
    timestep_k<<<BS_, TD_>>>(in_ts, temb0);
    tgemm_k<ACT_SILU,false,false,false><<<tgrid(BS_, D_, 1), 256>>>(
        BS_, D_, TD_, temb0, TD_, 0, te_w1, D_, 0, temb1, D_, 0, te_b1, nullptr, 1.f);
    tgemm_k<ACT_NONE,false,false,false><<<tgrid(BS_, D_, 1), 256>>>(
        BS_, D_, D_, temb1, D_, 0, te_w2, D_, 0, temb, D_, 0, te_b2, nullptr, 1.f);
    silu_k<<<(BS_*D_ + 255) / 256, 256>>>(temb, stemb, BS_ * D_);

    // --- proj_in + layer-invariant LN of xp (fp32 now; split handles precision) ---
    tgemm_k<ACT_NONE,false,false,false><<<tgrid(BS_*N1_, D_, 1), 256>>>(
        BS_*N1_, D_, ED_, in_x, ED_, 0, pin_w, D_, 0, xp, D_, 0, pin_b, nullptr, 1.f);
    ln_k<false><<<BS_*N1_, 256>>>(xp, xnorm, nullptr, nullptr);

    bcast_lat_k<<<(BS_*NQ_*D_ + 255) / 256, 256>>>(in_lat, lat, BS_*NQ_*D_, NQ_*D_);

    for (int l = 0; l < DEPTH; l++) {
        const float* wq_l  = wq  + (long)l * D_ * INNER;
        const float* wkv_l = wkv + (long)l * D_ * 2 * INNER;
        const float* wo_l  = wo  + (long)l * INNER * D_;
        const float* fw1_l = fw1 + (long)l * D_ * FF_;
        const float* fw2_l = fw2 + (long)l * FF_ * D_;
        const float* aw_l  = aw  + (long)l * D_ * 4 * D_;
        const float* ab_l  = ab  + (long)l * 4 * D_;
        const float* g1 = ln1_g + l * D_;
        const float* b1 = ln1_b + l * D_;
        const float* g2 = ln2_g + l * D_;
        const float* b2 = ln2_b + l * D_;
        const float* fg = flg + l * D_;
        const float* fb = flb + l * D_;

        // adaLN params
        tgemm_k<ACT_NONE,false,false,false><<<tgrid(BS_, 4*D_, 1), 256>>>(
            BS_, 4*D_, D_, stemb, D_, 0, aw_l, 4*D_, 0, ada, 4*D_, 0, ab_l, nullptr, 1.f);

        // latents LN + q projection + modulation
        ln_k<true><<<BS_*NQ_, 256>>>(lat, latn, g2, b2);
        tgemm_k<ACT_NONE,false,false,false><<<tgrid(BS_*NQ_, INNER, 1), 256>>>(
            BS_*NQ_, INNER, D_, latn, D_, 0, wq_l, INNER, 0, q, INNER, 0, nullptr, nullptr, 1.f);
        modulate_k<<<(BS_*NQ_*D_ + 255) / 256, 256>>>(q, ada);

        // qproj[b,q,h,d] = SCALE * qmod[b,q,h,:] @ wk_h^T   (batched over heads, BT)
        tgemm_k<ACT_NONE,false,false,true><<<tgrid(BS_*NQ_, D_, H_), 256>>>(
            BS_*NQ_, D_, DH_, q, INNER, 64, wkv_l, 2*INNER, 64,
            qp, H_*D_, (long)D_, nullptr, nullptr, SCALE_);

        // logits[b,(q,h),n] = (qproj .* g1) @ xnorm_b^T   (b1 drops: softmax shift-invariance)
        tgemm_k<ACT_NONE,false,true,true><<<tgrid(NQ_*H_, N1_, BS_), 256>>>(
            NQ_*H_, N1_, D_, qp, D_, (long)NQ_*H_*D_, xnorm, D_, (long)N1_*D_,
            att, N1_, (long)NQ_*H_*N1_, nullptr, g1, 1.f);

        softmax_k<<<BS_*NQ_*H_, 256>>>(att);

        // ov[b,(q,h),d] = attn @ xnorm_b
        tgemm_k<ACT_NONE,false,false,false><<<tgrid(NQ_*H_, D_, BS_), 256>>>(
            NQ_*H_, D_, N1_, att, N1_, (long)NQ_*H_*N1_, xnorm, D_, (long)N1_*D_,
            ov, D_, (long)NQ_*H_*D_, nullptr, nullptr, 1.f);

        // ov <- g1*ov + b1  (b1 survives: sum(attn)=1)
        ovmod_k<<<(BS_*NQ_*H_*D_ + 255) / 256, 256>>>(ov, g1, b1);

        // vout[b,q,h*64+dh] = ovm[b,q,h,:] @ wv_h   (batched over heads)
        tgemm_k<ACT_NONE,false,false,false><<<tgrid(BS_*NQ_, DH_, H_), 256>>>(
            BS_*NQ_, DH_, D_, ov, H_*D_, (long)D_, wkv_l + INNER, 2*INNER, 64,
            vout, D_, 64, nullptr, nullptr, 1.f);

        // lat += vout @ wo
        tgemm_k<ACT_NONE,true,false,false><<<tgrid(BS_*NQ_, D_, 1), 256>>>(
            BS_*NQ_, D_, INNER, vout, INNER, 0, wo_l, D_, 0, lat, D_, 0, nullptr, nullptr, 1.f);

        // FF block
        ln_k<true><<<BS_*NQ_, 256>>>(lat, hff, fg, fb);
        tgemm_k<ACT_GELU,false,false,false><<<tgrid(BS_*NQ_, FF_, 1), 256>>>(
            BS_*NQ_, FF_, D_, hff, D_, 0, fw1_l, FF_, 0, h1, FF_, 0, nullptr, nullptr, 1.f);
        tgemm_k<ACT_NONE,true,false,false><<<tgrid(BS_*NQ_, D_, 1), 256>>>(
            BS_*NQ_, D_, FF_, h1, FF_, 0, fw2_l, D_, 0, lat, D_, 0, nullptr, nullptr, 1.f);
    }

    // --- proj_out + final LN ---
    tgemm_k<ACT_NONE,false,false,false><<<tgrid(BS_*NQ_, D_, 1), 256>>>(
        BS_*NQ_, D_, D_, lat, D_, 0, pout_w, D_, 0, hff, D_, 0, pout_b, nullptr, 1.f);
    ln_k<true><<<BS_*NQ_, 256>>>(hff, out, ng, nb);
}

// round 6
// speedup vs baseline: 3.0372x; 2.9924x over previous
#include <cuda_runtime.h>
#include <cuda_bf16.h>
#include <math.h>
#include <stdint.h>

#define D_    1024
#define DEPTH 8
#define H_    16
#define DH_   64
#define INNER 1024
#define NQ_   8
#define ED_   768
#define FF_   4096
#define TD_   320
#define BS_   32
#define N1_   1024
#define SCALE_ 0.125f

#define ACT_NONE 0
#define ACT_SILU 1
#define ACT_GELU 2
#define CM_STORE 0
#define CM_ATOM  1

typedef __nv_bfloat16 bf;

// ---- fp32 scratch ----
__device__ float g_xp[BS_*N1_*D_];
__device__ float g_temb0[BS_*TD_];
__device__ float g_temb1[BS_*D_];
__device__ float g_temb[BS_*D_];
__device__ float g_stemb[BS_*D_];
__device__ float g_ada[BS_*4*D_];
__device__ float g_lat[BS_*NQ_*D_];
__device__ float g_q[BS_*NQ_*D_];
__device__ float g_qp[BS_*NQ_*H_*D_];
__device__ float g_att[BS_*NQ_*H_*N1_];
__device__ float g_ov[BS_*NQ_*H_*D_];
__device__ float g_vout[BS_*NQ_*D_];
__device__ float g_hff[BS_*NQ_*D_];
__device__ float g_h1[BS_*NQ_*FF_];

// ---- bf16 hi/lo pairs ----
__device__ bf s_inxH[BS_*N1_*ED_],  s_inxL[BS_*N1_*ED_];
__device__ bf s_pinH[D_*ED_],       s_pinL[D_*ED_];
__device__ bf s_xnH[BS_*N1_*D_],    s_xnL[BS_*N1_*D_];
__device__ bf s_xnTH[BS_*D_*N1_],   s_xnTL[BS_*D_*N1_];
__device__ bf s_latnH[BS_*NQ_*D_],  s_latnL[BS_*NQ_*D_];
__device__ bf s_qH[BS_*NQ_*D_],     s_qL[BS_*NQ_*D_];
__device__ bf s_qpH[BS_*NQ_*H_*D_], s_qpL[BS_*NQ_*H_*D_];
__device__ bf s_attH[BS_*NQ_*H_*N1_], s_attL[BS_*NQ_*H_*N1_];
__device__ bf s_ovH[BS_*NQ_*H_*D_], s_ovL[BS_*NQ_*H_*D_];
__device__ bf s_voH[BS_*NQ_*D_],    s_voL[BS_*NQ_*D_];
__device__ bf s_hffH[BS_*NQ_*D_],   s_hffL[BS_*NQ_*D_];
__device__ bf s_h1H[BS_*NQ_*FF_],   s_h1L[BS_*NQ_*FF_];
__device__ bf s_latH[BS_*NQ_*D_],   s_latL[BS_*NQ_*D_];
__device__ bf s_wqH[DEPTH*INNER*D_],  s_wqL[DEPTH*INNER*D_];
__device__ bf s_kvH[DEPTH*D_*2*INNER],s_kvL[DEPTH*D_*2*INNER];
__device__ bf s_kvTH[DEPTH*2*INNER*D_],s_kvTL[DEPTH*2*INNER*D_];
__device__ bf s_woH[DEPTH*D_*INNER],  s_woL[DEPTH*D_*INNER];
__device__ bf s_f1H[DEPTH*FF_*D_],    s_f1L[DEPTH*FF_*D_];
__device__ bf s_f2H[DEPTH*D_*FF_],    s_f2L[DEPTH*D_*FF_];
__device__ bf s_poH[D_*D_],           s_poL[D_*D_];

// ---- helpers ----
__device__ __forceinline__ uint32_t smem_u32(const void* p){
    uint32_t a;
    asm("{ .reg .u64 t; cvta.to.shared.u64 t, %1; cvt.u32.u64 %0, t; }":"=r"(a):"l"(p));
    return a;
}
__device__ __forceinline__ void sp2(float v, bf& h, bf& l){
    h = __float2bfloat16_rn(v);
    l = __float2bfloat16_rn(v - __bfloat162float(h));
}
#define CPA(d,s) asm volatile("cp.async.cg.shared.global [%0],[%1],16;"::"r"(d),"l"(s):"memory")
#define CPC()    asm volatile("cp.async.commit_group;":::"memory")
#define CPW(n)   asm volatile("cp.async.wait_group %0;"::"n"(n):"memory")
#define LDSM4(r,a) asm volatile("ldmatrix.sync.aligned.m8n8.x4.shared.b16 {%0,%1,%2,%3},[%4];" \
    :"=r"((r)[0]),"=r"((r)[1]),"=r"((r)[2]),"=r"((r)[3]):"r"(a))
#define MMA(d,a,b) asm volatile("mma.sync.aligned.m16n8k16.row.col.f32.bf16.bf16.f32 " \
    "{%0,%1,%2,%3},{%4,%5,%6,%7},{%8,%9},{%0,%1,%2,%3};" \
    :"+f"((d)[0]),"+f"((d)[1]),"+f"((d)[2]),"+f"((d)[3]) \
    :"r"((a)[0]),"r"((a)[1]),"r"((a)[2]),"r"((a)[3]),"r"((b)[0]),"r"((b)[1]))

// ---- bf16 tensor GEMM: C[M,N] = act(alpha*A@B^T (+bias)); A,B hi/lo bf16 K-major ----
// BM=128 BN=128 BK=32, 256 thr, double-buffered cp.async, 3-pass split accumulate.
template<int ACT,int CMODE>
__global__ void __launch_bounds__(256,1) mgemm(
    int M,int N,int K,int ksplit,
    const bf* __restrict__ Ah,const bf* __restrict__ Al,int lda,long sAz,
    const bf* __restrict__ Bh,const bf* __restrict__ Bl,int ldb,long sBz,
    float* __restrict__ C,int ldc,long sCz,
    const float* __restrict__ bias,float alpha)
{
    extern __shared__ bf sh[];
    const int t=threadIdx.x, lane=t&31, wid=t>>5;
    const int zz=blockIdx.z, batch=zz/ksplit, kp=zz-batch*ksplit;
    const int Kl=K/ksplit, koff=kp*Kl, NC=Kl>>5;
    const int bm=blockIdx.y*128, bn=blockIdx.x*128;
    Ah+=(long)batch*sAz; Al+=(long)batch*sAz;
    Bh+=(long)batch*sBz; Bl+=(long)batch*sBz;
    C +=(long)batch*sCz;
    const uint32_t sb = smem_u32(sh);
    const int mw=(wid>>2)*64, nw=(wid&3)*32;

    float acc[4][4][4];
#pragma unroll
    for(int a=0;a<4;a++)
#pragma unroll
    for(int b=0;b<4;b++)
#pragma unroll
    for(int c=0;c<4;c++) acc[a][b][c]=0.f;

    // fill stage st from k-chunk c
    auto fill=[&](int st,int c){
#pragma unroll
        for(int i=0;i<2;i++){
            int f=t+i*256, row=f>>2, ch=(f&3)*8;
            long ao=(long)(bm+row)*lda + koff + c*32 + ch;
            uint32_t d0 = sb + st*40960u + (uint32_t)(row*40+ch)*2u;
            CPA(d0,       Ah+ao);
            CPA(d0+10240, Al+ao);
            int rn=bn+row; if(rn>=N) rn=N-1;
            long bo=(long)rn*ldb + koff + c*32 + ch;
            CPA(d0+20480, Bh+bo);
            CPA(d0+30720, Bl+bo);
        }
        CPC();
    };

    fill(0,0);
    for(int c=0;c<NC;c++){
        int st=c&1;
        if(c+1<NC){ fill(st^1,c+1); CPW(1); } else { CPW(0); }
        __syncthreads();
        uint32_t base = sb + st*40960u;
#pragma unroll
        for(int ks=0;ks<2;ks++){
            uint32_t kadd = (uint32_t)(ks*32 + (lane>>4)*16);
            uint32_t Af[4][4], Bf[4][2];
            // pass0: Ah*Bh
#pragma unroll
            for(int mt=0;mt<4;mt++)
                LDSM4(Af[mt], base + (uint32_t)(mw+mt*16+(lane&15))*80u + kadd);
#pragma unroll
            for(int np=0;np<2;np++){
                uint32_t q[4];
                LDSM4(q, base+20480u + (uint32_t)(nw+np*16+(lane&15))*80u + kadd);
                Bf[np*2][0]=q[0]; Bf[np*2][1]=q[2];
                Bf[np*2+1][0]=q[1]; Bf[np*2+1][1]=q[3];
            }
#pragma unroll
            for(int mt=0;mt<4;mt++)
#pragma unroll
            for(int nt=0;nt<4;nt++) MMA(acc[mt][nt],Af[mt],Bf[nt]);
            // pass1: Al*Bh
#pragma unroll
            for(int mt=0;mt<4;mt++)
                LDSM4(Af[mt], base+10240u + (uint32_t)(mw+mt*16+(lane&15))*80u + kadd);
#pragma unroll
            for(int mt=0;mt<4;mt++)
#pragma unroll
            for(int nt=0;nt<4;nt++) MMA(acc[mt][nt],Af[mt],Bf[nt]);
            // pass2: Ah*Bl
#pragma unroll
            for(int mt=0;mt<4;mt++)
                LDSM4(Af[mt], base + (uint32_t)(mw+mt*16+(lane&15))*80u + kadd);
#pragma unroll
            for(int np=0;np<2;np++){
                uint32_t q[4];
                LDSM4(q, base+30720u + (uint32_t)(nw+np*16+(lane&15))*80u + kadd);
                Bf[np*2][0]=q[0]; Bf[np*2][1]=q[2];
                Bf[np*2+1][0]=q[1]; Bf[np*2+1][1]=q[3];
            }
#pragma unroll
            for(int mt=0;mt<4;mt++)
#pragma unroll
            for(int nt=0;nt<4;nt++) MMA(acc[mt][nt],Af[mt],Bf[nt]);
        }
        __syncthreads();
    }

    const bool dob = bias && kp==0;
#pragma unroll
    for(int mt=0;mt<4;mt++)
#pragma unroll
    for(int nt=0;nt<4;nt++){
        int gc = bn+nw+nt*8+(lane&3)*2;
#pragma unroll
        for(int rr=0;rr<2;rr++){
            int gr = bm+mw+mt*16+(lane>>2)+rr*8;
            if(gr>=M) continue;
#pragma unroll
            for(int cc=0;cc<2;cc++){
                int c2=gc+cc;
                if(c2>=N) continue;
                float v = acc[mt][nt][rr*2+cc]*alpha;
                if(dob) v += bias[c2];
                if(ACT==ACT_SILU) v = v/(1.f+expf(-v));
                if(ACT==ACT_GELU) v = 0.5f*v*(1.f+erff(v*0.70710678118654752f));
                long off=(long)gr*ldc+c2;
                if(CMODE==CM_ATOM) atomicAdd(&C[off],v); else C[off]=v;
            }
        }
    }
}

// ---- SIMT fp32 GEMM (small M: temb, adaLN). B row-major [K][N]. ----
template<int ACT>
__global__ void __launch_bounds__(256) gemm_s(
    int M,int N,int K,
    const float* __restrict__ A,int lda,
    const float* __restrict__ B,int ldb,
    float* __restrict__ C,int ldc,
    const float* __restrict__ bias)
{
    __shared__ float As[16][68], Bs[16][68];
    int bm=blockIdx.y*64, bn=blockIdx.x*64, t=threadIdx.x;
    int tx=t&15, ty=t>>4;
    float acc[4][4];
#pragma unroll
    for(int i=0;i<4;i++)
#pragma unroll
    for(int j=0;j<4;j++) acc[i][j]=0.f;
    for(int k0=0;k0<K;k0+=16){
#pragma unroll
        for(int i=0;i<4;i++){
            int idx=t+i*256, r=idx>>4, kk=idx&15;
            As[kk][r] = (bm+r<M)? A[(long)(bm+r)*lda+k0+kk] : 0.f;
        }
#pragma unroll
        for(int i=0;i<4;i++){
            int idx=t+i*256, kk=idx>>6, cc=idx&63;
            Bs[kk][cc] = (bn+cc<N)? B[(long)(k0+kk)*ldb+bn+cc] : 0.f;
        }
        __syncthreads();
#pragma unroll
        for(int kk=0;kk<16;kk++){
            float ra[4],rb[4];
#pragma unroll
            for(int i=0;i<4;i++) ra[i]=As[kk][ty*4+i];
#pragma unroll
            for(int j=0;j<4;j++) rb[j]=Bs[kk][tx*4+j];
#pragma unroll
            for(int i=0;i<4;i++)
#pragma unroll
            for(int j=0;j<4;j++) acc[i][j]+=ra[i]*rb[j];
        }
        __syncthreads();
    }
#pragma unroll
    for(int i=0;i<4;i++){
        int gr=bm+ty*4+i; if(gr>=M) continue;
#pragma unroll
        for(int j=0;j<4;j++){
            int gc=bn+tx*4+j; if(gc>=N) continue;
            float v=acc[i][j];
            if(bias) v+=bias[gc];
            if(ACT==ACT_SILU) v=v/(1.f+expf(-v));
            C[(long)gr*ldc+gc]=v;
        }
    }
}

// ---- LayerNorm D=1024 -> split pair (or fp32) ----
template<bool AFFINE,bool SPLIT>
__global__ void __launch_bounds__(256) ln_k(const float* __restrict__ x,
    float* __restrict__ y, bf* __restrict__ yH, bf* __restrict__ yL,
    const float* __restrict__ g, const float* __restrict__ b)
{
    long row=blockIdx.x; const float* xr=x+row*D_; int t=threadIdx.x;
    float v[4], s=0.f;
#pragma unroll
    for(int i=0;i<4;i++){ v[i]=xr[t+i*256]; s+=v[i]; }
    __shared__ float red[256];
    red[t]=s; __syncthreads();
    for(int o=128;o>0;o>>=1){ if(t<o) red[t]+=red[t+o]; __syncthreads(); }
    float m=red[0]*(1.f/D_); __syncthreads();
    float vs=0.f;
#pragma unroll
    for(int i=0;i<4;i++){ float d=v[i]-m; vs+=d*d; }
    red[t]=vs; __syncthreads();
    for(int o=128;o>0;o>>=1){ if(t<o) red[t]+=red[t+o]; __syncthreads(); }
    float rs=1.f/sqrtf(red[0]*(1.f/D_)+1e-5f);
#pragma unroll
    for(int i=0;i<4;i++){
        int c=t+i*256; float o=(v[i]-m)*rs;
        if(AFFINE) o=o*g[c]+b[c];
        if(SPLIT){ bf h,l; sp2(o,h,l); yH[row*D_+c]=h; yL[row*D_+c]=l; }
        else y[row*D_+c]=o;
    }
}

// ---- softmax 1024 -> split pair ----
__global__ void __launch_bounds__(256) softmax_k(const float* __restrict__ x,
    bf* __restrict__ pH, bf* __restrict__ pL)
{
    long row=blockIdx.x; const float* p=x+row*N1_; int t=threadIdx.x;
    float v[4], mx=-1e30f;
#pragma unroll
    for(int i=0;i<4;i++){ v[i]=p[t+i*256]; mx=fmaxf(mx,v[i]); }
    __shared__ float red[256];
    red[t]=mx; __syncthreads();
    for(int o=128;o>0;o>>=1){ if(t<o) red[t]=fmaxf(red[t],red[t+o]); __syncthreads(); }
    mx=red[0]; __syncthreads();
    float s=0.f;
#pragma unroll
    for(int i=0;i<4;i++){ v[i]=expf(v[i]-mx); s+=v[i]; }
    red[t]=s; __syncthreads();
    for(int o=128;o>0;o>>=1){ if(t<o) red[t]+=red[t+o]; __syncthreads(); }
    float inv=1.f/red[0];
#pragma unroll
    for(int i=0;i<4;i++){
        int c=t+i*256; bf h,l; sp2(v[i]*inv,h,l);
        pH[row*N1_+c]=h; pL[row*N1_+c]=l;
    }
}

// ---- split fp32 -> hi/lo (optional per-col scale, cols=1024) ----
__global__ void split_k(const float* __restrict__ s, bf* __restrict__ h, bf* __restrict__ l,
                        int n, const float* __restrict__ scale)
{
    int i=blockIdx.x*blockDim.x+threadIdx.x;
    if(i>=n) return;
    float v=s[i];
    if(scale) v*=scale[i&1023];
    bf hh,ll; sp2(v,hh,ll); h[i]=hh; l[i]=ll;
}

// ---- transpose+split fp32 [K][N] -> pairs [N][K], z-batched ----
__global__ void wsplitT(const float* __restrict__ src, bf* __restrict__ th, bf* __restrict__ tl,
                        int K,int N,long sz)
{
    __shared__ float tile[32][33];
    int z=blockIdx.z;
    const float* S=src+(long)z*sz;
    bf* TH=th+(long)z*sz; bf* TL=tl+(long)z*sz;
    int n0=blockIdx.x*32, k0=blockIdx.y*32;
    int tx=threadIdx.x, ty=threadIdx.y;
#pragma unroll
    for(int j=0;j<4;j++){
        int k=k0+ty+j*8;
        tile[ty+j*8][tx] = (k<K && n0+tx<N)? S[(long)k*N+n0+tx] : 0.f;
    }
    __syncthreads();
#pragma unroll
    for(int j=0;j<4;j++){
        int n=n0+ty+j*8, k=k0+tx;
        if(n<N && k<K){ bf h,l; sp2(tile[tx][ty+j*8],h,l);
            TH[(long)n*K+k]=h; TL[(long)n*K+k]=l; }
    }
}

// ---- transpose bf16 pairs [R][C] -> [C][R], z-batched ----
__global__ void btransp(const bf* __restrict__ ih,const bf* __restrict__ il,
                        bf* __restrict__ oh, bf* __restrict__ ol,int R,int C)
{
    __shared__ bf th[32][33], tl[32][33];
    long zo=(long)blockIdx.z*R*C;
    int c0=blockIdx.x*32, r0=blockIdx.y*32;
    int tx=threadIdx.x, ty=threadIdx.y;
#pragma unroll
    for(int j=0;j<4;j++){
        int r=r0+ty+j*8;
        th[ty+j*8][tx]=ih[zo+(long)r*C+c0+tx];
        tl[ty+j*8][tx]=il[zo+(long)r*C+c0+tx];
    }
    __syncthreads();
#pragma unroll
    for(int j=0;j<4;j++){
        int c=c0+ty+j*8, r=r0+tx;
        oh[zo+(long)c*R+r]=th[tx][ty+j*8];
        ol[zo+(long)c*R+r]=tl[tx][ty+j*8];
    }
}

// ---- misc ----
__global__ void timestep_k(const float* __restrict__ ts, float* __restrict__ out){
    int b=blockIdx.x,i=threadIdx.x;
    int j=(i<160)?i:(i-160);
    float f=expf(-logf(10000.f)*(float)j/160.f);
    double a=(double)(ts[b]*f);
    out[b*TD_+i]=(i<160)?(float)cos(a):(float)sin(a);
}
__global__ void silu_k(const float* __restrict__ x,float* __restrict__ y,int n){
    int i=blockIdx.x*blockDim.x+threadIdx.x;
    if(i<n){ float v=x[i]; y[i]=v/(1.f+expf(-v)); }
}
__global__ void bcast_k(const float* __restrict__ s,float* __restrict__ d,int n,int per){
    int i=blockIdx.x*blockDim.x+threadIdx.x;
    if(i<n) d[i]=s[i%per];
}
__global__ void modulate_k(const float* __restrict__ q,const float* __restrict__ ada,
                           bf* __restrict__ qH,bf* __restrict__ qL){
    int i=blockIdx.x*blockDim.x+threadIdx.x;
    if(i>=BS_*NQ_*D_) return;
    int b=i/(NQ_*D_), c=i&(D_-1);
    float v=q[i]*(1.f+ada[b*4*D_+2*D_+c])+ada[b*4*D_+c];
    bf h,l; sp2(v,h,l); qH[i]=h; qL[i]=l;
}
__global__ void ovmod_k(const float* __restrict__ ov,const float* __restrict__ g1,
                        const float* __restrict__ b1,bf* __restrict__ oH,bf* __restrict__ oL){
    int i=blockIdx.x*blockDim.x+threadIdx.x;
    if(i>=BS_*NQ_*H_*D_) return;
    int d=i&(D_-1);
    float v=g1[d]*ov[i]+b1[d];
    bf h,l; sp2(v,h,l); oH[i]=h; oL[i]=l;
}
__global__ void zero_k(float* __restrict__ p,int n){
    int i=blockIdx.x*blockDim.x+threadIdx.x;
    if(i<n) p[i]=0.f;
}

// ---- host ----
#define GSA(p,s) cudaGetSymbolAddress((void**)&p,s)
static inline dim3 tg(int M,int N,int z){ return dim3((unsigned)((N+127)/128),(unsigned)((M+127)/128),(unsigned)z); }
#define SMB 81920

extern "C" void kernel_launch(void* const* d_in, const int* in_sizes, int n_in,
                              void* d_out, int out_size)
{
    const float *in_x=(const float*)d_in[0], *in_ts=(const float*)d_in[1], *in_lat=(const float*)d_in[2];
    const float *te_w1=(const float*)d_in[3], *te_b1=(const float*)d_in[4];
    const float *te_w2=(const float*)d_in[5], *te_b2=(const float*)d_in[6];
    const float *pin_w=(const float*)d_in[7], *pin_b=(const float*)d_in[8];
    const float *ln1_g=(const float*)d_in[9], *ln1_b=(const float*)d_in[10];
    const float *ln2_g=(const float*)d_in[11], *ln2_b=(const float*)d_in[12];
    const float *wq=(const float*)d_in[13], *wkv=(const float*)d_in[14], *wo=(const float*)d_in[15];
    const float *flg=(const float*)d_in[16], *flb=(const float*)d_in[17];
    const float *fw1=(const float*)d_in[18], *fw2=(const float*)d_in[19];
    const float *aw=(const float*)d_in[20], *ab=(const float*)d_in[21];
    const float *pout_w=(const float*)d_in[22], *pout_b=(const float*)d_in[23];
    const float *ng=(const float*)d_in[24], *nb=(const float*)d_in[25];
    float* out=(float*)d_out;

    cudaFuncSetAttribute(mgemm<ACT_NONE,CM_STORE>,cudaFuncAttributeMaxDynamicSharedMemorySize,SMB);
    cudaFuncSetAttribute(mgemm<ACT_GELU,CM_STORE>,cudaFuncAttributeMaxDynamicSharedMemorySize,SMB);
    cudaFuncSetAttribute(mgemm<ACT_NONE,CM_ATOM>, cudaFuncAttributeMaxDynamicSharedMemorySize,SMB);

    float *xp,*temb0,*temb1,*temb,*stemb,*ada,*lat,*q,*qp,*att,*ov,*vout,*hff,*h1;
    GSA(xp,g_xp); GSA(temb0,g_temb0); GSA(temb1,g_temb1); GSA(temb,g_temb);
    GSA(stemb,g_stemb); GSA(ada,g_ada); GSA(lat,g_lat); GSA(q,g_q); GSA(qp,g_qp);
    GSA(att,g_att); GSA(ov,g_ov); GSA(vout,g_vout); GSA(hff,g_hff); GSA(h1,g_h1);
    bf *inxH,*inxL,*pinH,*pinL,*xnH,*xnL,*xnTH,*xnTL,*latnH,*latnL,*qH,*qL,*qpH,*qpL;
    bf *attH,*attL,*ovH,*ovL,*voH,*voL,*hffH,*hffL,*h1H,*h1L,*latH,*latL;
    bf *wqH,*wqL,*kvH,*kvL,*kvTH,*kvTL,*woH,*woL,*f1H,*f1L,*f2H,*f2L,*poH,*poL;
    GSA(inxH,s_inxH); GSA(inxL,s_inxL); GSA(pinH,s_pinH); GSA(pinL,s_pinL);
    GSA(xnH,s_xnH); GSA(xnL,s_xnL); GSA(xnTH,s_xnTH); GSA(xnTL,s_xnTL);
    GSA(latnH,s_latnH); GSA(latnL,s_latnL); GSA(qH,s_qH); GSA(qL,s_qL);
    GSA(qpH,s_qpH); GSA(qpL,s_qpL); GSA(attH,s_attH); GSA(attL,s_attL);
    GSA(ovH,s_ovH); GSA(ovL,s_ovL); GSA(voH,s_voH); GSA(voL,s_voL);
    GSA(hffH,s_hffH); GSA(hffL,s_hffL); GSA(h1H,s_h1H); GSA(h1L,s_h1L);
    GSA(latH,s_latH); GSA(latL,s_latL);
    GSA(wqH,s_wqH); GSA(wqL,s_wqL); GSA(kvH,s_kvH); GSA(kvL,s_kvL);
    GSA(kvTH,s_kvTH); GSA(kvTL,s_kvTL); GSA(woH,s_woH); GSA(woL,s_woL);
    GSA(f1H,s_f1H); GSA(f1L,s_f1L); GSA(f2H,s_f2H); GSA(f2L,s_f2L);
    GSA(poH,s_poH); GSA(poL,s_poL);

    dim3 t32(32,8);
    // ---- weight prep (once per call) ----
    wsplitT<<<dim3(D_/32,ED_/32,1),t32>>>(pin_w,pinH,pinL,ED_,D_,0);
    wsplitT<<<dim3(INNER/32,D_/32,DEPTH),t32>>>(wq,wqH,wqL,D_,INNER,(long)D_*INNER);
    split_k<<<(DEPTH*D_*2*INNER+255)/256,256>>>(wkv,kvH,kvL,DEPTH*D_*2*INNER,nullptr);
    wsplitT<<<dim3(2*INNER/32,D_/32,DEPTH),t32>>>(wkv,kvTH,kvTL,D_,2*INNER,(long)D_*2*INNER);
    wsplitT<<<dim3(D_/32,INNER/32,DEPTH),t32>>>(wo,woH,woL,INNER,D_,(long)INNER*D_);
    wsplitT<<<dim3(FF_/32,D_/32,DEPTH),t32>>>(fw1,f1H,f1L,D_,FF_,(long)D_*FF_);
    wsplitT<<<dim3(D_/32,FF_/32,DEPTH),t32>>>(fw2,f2H,f2L,FF_,D_,(long)FF_*D_);
    wsplitT<<<dim3(D_/32,D_/32,1),t32>>>(pout_w,poH,poL,D_,D_,0);
    split_k<<<(BS_*N1_*ED_+255)/256,256>>>(in_x,inxH,inxL,BS_*N1_*ED_,nullptr);

    // ---- timestep embedding (SIMT) ----
    timestep_k<<<BS_,TD_>>>(in_ts,temb0);
    gemm_s<ACT_SILU><<<dim3(16,1),256>>>(BS_,D_,TD_,temb0,TD_,te_w1,D_,temb1,D_,te_b1);
    gemm_s<ACT_NONE><<<dim3(16,1),256>>>(BS_,D_,D_,temb1,D_,te_w2,D_,temb,D_,te_b2);
    silu_k<<<(BS_*D_+255)/256,256>>>(temb,stemb,BS_*D_);

    // ---- proj_in + layer-invariant LN + transpose ----
    mgemm<ACT_NONE,CM_STORE><<<tg(BS_*N1_,D_,1),256,SMB>>>(
        BS_*N1_,D_,ED_,1, inxH,inxL,ED_,0, pinH,pinL,ED_,0, xp,D_,0, pin_b,1.f);
    ln_k<false,true><<<BS_*N1_,256>>>(xp,nullptr,xnH,xnL,nullptr,nullptr);
    btransp<<<dim3(D_/32,N1_/32,BS_),t32>>>(xnH,xnL,xnTH,xnTL,N1_,D_);
    bcast_k<<<(BS_*NQ_*D_+255)/256,256>>>(in_lat,lat,BS_*NQ_*D_,NQ_*D_);

    for(int l=0;l<DEPTH;l++){
        const float *g1=ln1_g+l*D_, *b1=ln1_b+l*D_, *g2=ln2_g+l*D_, *b2=ln2_b+l*D_;
        const float *fg=flg+l*D_, *fb=flb+l*D_;
        const bf *wqh=wqH+(long)l*INNER*D_, *wql=wqL+(long)l*INNER*D_;
        const bf *kvh=kvH+(long)l*D_*2*INNER, *kvl=kvL+(long)l*D_*2*INNER;
        const bf *kvth=kvTH+(long)l*2*INNER*D_, *kvtl=kvTL+(long)l*2*INNER*D_;
        const bf *woh=woH+(long)l*D_*INNER, *wol=woL+(long)l*D_*INNER;
        const bf *f1h=f1H+(long)l*FF_*D_, *f1l=f1L+(long)l*FF_*D_;
        const bf *f2h=f2H+(long)l*D_*FF_, *f2l=f2L+(long)l*D_*FF_;

        // adaLN (SIMT, M=32)
        gemm_s<ACT_NONE><<<dim3(64,1),256>>>(BS_,4*D_,D_,stemb,D_,aw+(long)l*D_*4*D_,4*D_,ada,4*D_,ab+(long)l*4*D_);

        // latn -> q (split-K=8) -> modulate
        ln_k<true,true><<<BS_*NQ_,256>>>(lat,nullptr,latnH,latnL,g2,b2);
        zero_k<<<(BS_*NQ_*D_+255)/256,256>>>(q,BS_*NQ_*D_);
        mgemm<ACT_NONE,CM_ATOM><<<tg(BS_*NQ_,INNER,8),256,SMB>>>(
            BS_*NQ_,INNER,D_,8, latnH,latnL,D_,0, wqh,wql,D_,0, q,INNER,0, nullptr,1.f);
        modulate_k<<<(BS_*NQ_*D_+255)/256,256>>>(q,ada,qH,qL);

        // qp = SCALE * qmod_h @ wk_h^T (z=heads)
        mgemm<ACT_NONE,CM_STORE><<<tg(BS_*NQ_,D_,H_),256,SMB>>>(
            BS_*NQ_,D_,DH_,1, qH,qL,INNER,64, kvh,kvl,2*INNER,64,
            qp,H_*D_,(long)D_, nullptr,SCALE_);
        split_k<<<(BS_*NQ_*H_*D_+255)/256,256>>>(qp,qpH,qpL,BS_*NQ_*H_*D_,g1);

        // logits = (qp*g1) @ xn^T (z=batch); b1 drops (softmax shift-invariant)
        mgemm<ACT_NONE,CM_STORE><<<tg(NQ_*H_,N1_,BS_),256,SMB>>>(
            NQ_*H_,N1_,D_,1, qpH,qpL,D_,(long)NQ_*H_*D_, xnH,xnL,D_,(long)N1_*D_,
            att,N1_,(long)NQ_*H_*N1_, nullptr,1.f);
        softmax_k<<<BS_*NQ_*H_,256>>>(att,attH,attL);

        // ov = attn @ xn (z=batch, via xnT)
        mgemm<ACT_NONE,CM_STORE><<<tg(NQ_*H_,D_,BS_),256,SMB>>>(
            NQ_*H_,D_,N1_,1, attH,attL,N1_,(long)NQ_*H_*N1_, xnTH,xnTL,N1_,(long)D_*N1_,
            ov,D_,(long)NQ_*H_*D_, nullptr,1.f);
        ovmod_k<<<(BS_*NQ_*H_*D_+255)/256,256>>>(ov,g1,b1,ovH,ovL);

        // vout = ovm_h @ wv_h (z=heads, split-K=4)
        zero_k<<<(BS_*NQ_*D_+255)/256,256>>>(vout,BS_*NQ_*D_);
        mgemm<ACT_NONE,CM_ATOM><<<tg(BS_*NQ_,DH_,H_*4),256,SMB>>>(
            BS_*NQ_,DH_,D_,4, ovH,ovL,H_*D_,(long)D_, kvth+(long)INNER*D_,kvtl+(long)INNER*D_,D_,(long)64*D_,
            vout,D_,64, nullptr,1.f);
        split_k<<<(BS_*NQ_*D_+255)/256,256>>>(vout,voH,voL,BS_*NQ_*D_,nullptr);

        // lat += vout @ wo (split-K=8, atomic into residual)
        mgemm<ACT_NONE,CM_ATOM><<<tg(BS_*NQ_,D_,8),256,SMB>>>(
            BS_*NQ_,D_,INNER,8, voH,voL,INNER,0, woh,wol,INNER,0, lat,D_,0, nullptr,1.f);

        // FF
        ln_k<true,true><<<BS_*NQ_,256>>>(lat,nullptr,hffH,hffL,fg,fb);
        mgemm<ACT_GELU,CM_STORE><<<tg(BS_*NQ_,FF_,1),256,SMB>>>(
            BS_*NQ_,FF_,D_,1, hffH,hffL,D_,0, f1h,f1l,D_,0, h1,FF_,0, nullptr,1.f);
        split_k<<<(BS_*NQ_*FF_+255)/256,256>>>(h1,h1H,h1L,BS_*NQ_*FF_,nullptr);
        mgemm<ACT_NONE,CM_ATOM><<<tg(BS_*NQ_,D_,8),256,SMB>>>(
            BS_*NQ_,D_,FF_,8, h1H,h1L,FF_,0, f2h,f2l,FF_,0, lat,D_,0, nullptr,1.f);
    }

    // ---- proj_out (split-K=8) + final LN ----
    split_k<<<(BS_*NQ_*D_+255)/256,256>>>(lat,latH,latL,BS_*NQ_*D_,nullptr);
    zero_k<<<(BS_*NQ_*D_+255)/256,256>>>(hff,BS_*NQ_*D_);
    mgemm<ACT_NONE,CM_ATOM><<<tg(BS_*NQ_,D_,8),256,SMB>>>(
        BS_*NQ_,D_,D_,8, latH,latL,D_,0, poH,poL,D_,0, hff,D_,0, pout_b,1.f);
    ln_k<true,false><<<BS_*NQ_,256>>>(hff,out,nullptr,nullptr,ng,nb);
}

// round 7
// speedup vs baseline: 3.7137x; 1.2228x over previous
#include <cuda_runtime.h>
#include <cuda_bf16.h>
#include <math.h>
#include <stdint.h>

#define D_    1024
#define DEPTH 8
#define H_    16
#define DH_   64
#define INNER 1024
#define NQ_   8
#define ED_   768
#define FF_   4096
#define TD_   320
#define BS_   32
#define N1_   1024
#define SCALE_ 0.125f
#define ADAW  32768

#define ACT_NONE 0
#define ACT_SILU 1
#define CM_STORE 0
#define CM_ATOM  1
#define CM_SPLIT 2

typedef __nv_bfloat16 bf;

// ---- fp32 scratch ----
__device__ float g_xp[BS_*N1_*D_];
__device__ float g_temb0[BS_*TD_];
__device__ float g_temb1[BS_*D_];
__device__ float g_temb[BS_*D_];
__device__ float g_stemb[BS_*D_];
__device__ float g_ada[BS_*ADAW];
__device__ float g_lat[BS_*NQ_*D_];
__device__ float g_q[BS_*NQ_*D_];
__device__ float g_att[BS_*NQ_*H_*N1_];
__device__ float g_vout[BS_*NQ_*D_];
__device__ float g_hff[BS_*NQ_*D_];
__device__ float g_h1[BS_*NQ_*FF_];

// ---- bf16 hi/lo pairs ----
__device__ bf s_inxH[BS_*N1_*ED_],  s_inxL[BS_*N1_*ED_];
__device__ bf s_pinH[D_*ED_],       s_pinL[D_*ED_];
__device__ bf s_xnH[BS_*N1_*D_],    s_xnL[BS_*N1_*D_];
__device__ bf s_xnTH[BS_*D_*N1_],   s_xnTL[BS_*D_*N1_];
__device__ bf s_latnH[BS_*NQ_*D_],  s_latnL[BS_*NQ_*D_];
__device__ bf s_qH[BS_*NQ_*D_],     s_qL[BS_*NQ_*D_];
__device__ bf s_qpH[BS_*NQ_*H_*D_], s_qpL[BS_*NQ_*H_*D_];
__device__ bf s_attH[BS_*NQ_*H_*N1_], s_attL[BS_*NQ_*H_*N1_];
__device__ bf s_ovH[BS_*NQ_*H_*D_], s_ovL[BS_*NQ_*H_*D_];
__device__ bf s_voH[BS_*NQ_*D_],    s_voL[BS_*NQ_*D_];
__device__ bf s_hffH[BS_*NQ_*D_],   s_hffL[BS_*NQ_*D_];
__device__ bf s_h1H[BS_*NQ_*FF_],   s_h1L[BS_*NQ_*FF_];
__device__ bf s_latH[BS_*NQ_*D_],   s_latL[BS_*NQ_*D_];
__device__ bf s_stH[BS_*D_],        s_stL[BS_*D_];
__device__ bf s_wqH[DEPTH*INNER*D_],  s_wqL[DEPTH*INNER*D_];
__device__ bf s_kvH[DEPTH*D_*2*INNER],s_kvL[DEPTH*D_*2*INNER];
__device__ bf s_kvTH[DEPTH*2*INNER*D_],s_kvTL[DEPTH*2*INNER*D_];
__device__ bf s_woH[DEPTH*D_*INNER],  s_woL[DEPTH*D_*INNER];
__device__ bf s_f1H[DEPTH*FF_*D_],    s_f1L[DEPTH*FF_*D_];
__device__ bf s_f2H[DEPTH*D_*FF_],    s_f2L[DEPTH*D_*FF_];
__device__ bf s_awH[DEPTH*4*D_*D_],   s_awL[DEPTH*4*D_*D_];
__device__ bf s_poH[D_*D_],           s_poL[D_*D_];

// ---- helpers ----
__device__ __forceinline__ uint32_t smem_u32(const void* p){
    uint32_t a;
    asm("{ .reg .u64 t; cvta.to.shared.u64 t, %1; cvt.u32.u64 %0, t; }":"=r"(a):"l"(p));
    return a;
}
__device__ __forceinline__ void sp2(float v, bf& h, bf& l){
    h = __float2bfloat16_rn(v);
    l = __float2bfloat16_rn(v - __bfloat162float(h));
}
#define CPA(d,s) asm volatile("cp.async.cg.shared.global [%0],[%1],16;"::"r"(d),"l"(s):"memory")
#define CPC()    asm volatile("cp.async.commit_group;":::"memory")
#define CPW(n)   asm volatile("cp.async.wait_group %0;"::"n"(n):"memory")
#define LDSM4(r,a) asm volatile("ldmatrix.sync.aligned.m8n8.x4.shared.b16 {%0,%1,%2,%3},[%4];" \
    :"=r"((r)[0]),"=r"((r)[1]),"=r"((r)[2]),"=r"((r)[3]):"r"(a))
#define MMA(d,a,b) asm volatile("mma.sync.aligned.m16n8k16.row.col.f32.bf16.bf16.f32 " \
    "{%0,%1,%2,%3},{%4,%5,%6,%7},{%8,%9},{%0,%1,%2,%3};" \
    :"+f"((d)[0]),"+f"((d)[1]),"+f"((d)[2]),"+f"((d)[3]) \
    :"r"((a)[0]),"r"((a)[1]),"r"((a)[2]),"r"((a)[3]),"r"((b)[0]),"r"((b)[1]))

// ---- bf16 tensor GEMM: C = A@B^T (3-pass hi/lo); outputs fp32 (store/atom) or split pair ----
template<int CMODE>
__global__ void __launch_bounds__(256,2) mgemm(
    int M,int N,int K,int ksplit,
    const bf* __restrict__ Ah,const bf* __restrict__ Al,int lda,long sAz,
    const bf* __restrict__ Bh,const bf* __restrict__ Bl,int ldb,long sBz,
    float* __restrict__ C, bf* __restrict__ CH, bf* __restrict__ CL, int ldc, long sCz,
    const float* __restrict__ bias, const float* __restrict__ cscale, float alpha)
{
    extern __shared__ bf sh[];
    const int t=threadIdx.x, lane=t&31, wid=t>>5;
    const int zz=blockIdx.z, batch=zz/ksplit, kp=zz-batch*ksplit;
    const int Kl=K/ksplit, koff=kp*Kl, NC=Kl>>5;
    const int bm=blockIdx.y*128, bn=blockIdx.x*128;
    Ah+=(long)batch*sAz; Al+=(long)batch*sAz;
    Bh+=(long)batch*sBz; Bl+=(long)batch*sBz;
    const uint32_t sb = smem_u32(sh);
    const int mw=(wid>>2)*64, nw=(wid&3)*32;

    float acc[4][4][4];
#pragma unroll
    for(int a=0;a<4;a++)
#pragma unroll
    for(int b=0;b<4;b++)
#pragma unroll
    for(int c=0;c<4;c++) acc[a][b][c]=0.f;

    auto fill=[&](int st,int c){
#pragma unroll
        for(int i=0;i<2;i++){
            int f=t+i*256, row=f>>2, ch=(f&3)*8;
            long ao=(long)(bm+row)*lda + koff + c*32 + ch;
            uint32_t d0 = sb + st*40960u + (uint32_t)(row*40+ch)*2u;
            CPA(d0,       Ah+ao);
            CPA(d0+10240, Al+ao);
            int rn=bn+row; if(rn>=N) rn=N-1;
            long bo=(long)rn*ldb + koff + c*32 + ch;
            CPA(d0+20480, Bh+bo);
            CPA(d0+30720, Bl+bo);
        }
        CPC();
    };

    fill(0,0);
    for(int c=0;c<NC;c++){
        int st=c&1;
        if(c+1<NC){ fill(st^1,c+1); CPW(1); } else { CPW(0); }
        __syncthreads();
        uint32_t base = sb + st*40960u;
#pragma unroll
        for(int ks=0;ks<2;ks++){
            uint32_t kadd = (uint32_t)(ks*32 + (lane>>4)*16);
            uint32_t Af[4][4], Bh2[4][2], Bl2[4][2];
            // load Ah + Bh
#pragma unroll
            for(int mt=0;mt<4;mt++)
                LDSM4(Af[mt], base + (uint32_t)(mw+mt*16+(lane&15))*80u + kadd);
#pragma unroll
            for(int np=0;np<2;np++){
                uint32_t qq[4];
                LDSM4(qq, base+20480u + (uint32_t)(nw+np*16+(lane&15))*80u + kadd);
                Bh2[np*2][0]=qq[0]; Bh2[np*2][1]=qq[2];
                Bh2[np*2+1][0]=qq[1]; Bh2[np*2+1][1]=qq[3];
            }
            // pass0: Ah*Bh
#pragma unroll
            for(int mt=0;mt<4;mt++)
#pragma unroll
            for(int nt=0;nt<4;nt++) MMA(acc[mt][nt],Af[mt],Bh2[nt]);
            // load Bl; pass1: Ah*Bl (Af kept)
#pragma unroll
            for(int np=0;np<2;np++){
                uint32_t qq[4];
                LDSM4(qq, base+30720u + (uint32_t)(nw+np*16+(lane&15))*80u + kadd);
                Bl2[np*2][0]=qq[0]; Bl2[np*2][1]=qq[2];
                Bl2[np*2+1][0]=qq[1]; Bl2[np*2+1][1]=qq[3];
            }
#pragma unroll
            for(int mt=0;mt<4;mt++)
#pragma unroll
            for(int nt=0;nt<4;nt++) MMA(acc[mt][nt],Af[mt],Bl2[nt]);
            // load Al; pass2: Al*Bh (Bh2 kept)
#pragma unroll
            for(int mt=0;mt<4;mt++)
                LDSM4(Af[mt], base+10240u + (uint32_t)(mw+mt*16+(lane&15))*80u + kadd);
#pragma unroll
            for(int mt=0;mt<4;mt++)
#pragma unroll
            for(int nt=0;nt<4;nt++) MMA(acc[mt][nt],Af[mt],Bh2[nt]);
        }
        __syncthreads();
    }

    const bool dob = bias && (CMODE!=CM_ATOM || kp==0);
#pragma unroll
    for(int mt=0;mt<4;mt++)
#pragma unroll
    for(int nt=0;nt<4;nt++){
        int gc = bn+nw+nt*8+(lane&3)*2;
#pragma unroll
        for(int rr=0;rr<2;rr++){
            int gr = bm+mw+mt*16+(lane>>2)+rr*8;
            if(gr>=M) continue;
#pragma unroll
            for(int cc=0;cc<2;cc++){
                int c2=gc+cc;
                if(c2>=N) continue;
                float v = acc[mt][nt][rr*2+cc]*alpha;
                if(cscale) v *= cscale[c2];
                if(dob) v += bias[c2];
                long off=(long)batch*sCz + (long)gr*ldc + c2;
                if(CMODE==CM_ATOM) atomicAdd(&C[off],v);
                else if(CMODE==CM_STORE) C[off]=v;
                else { bf h,l; sp2(v,h,l); CH[off]=h; CL[off]=l; }
            }
        }
    }
}

// ---- SIMT fp32 GEMM (temb only) ----
template<int ACT>
__global__ void __launch_bounds__(256) gemm_s(
    int M,int N,int K,
    const float* __restrict__ A,int lda,
    const float* __restrict__ B,int ldb,
    float* __restrict__ C,int ldc,
    const float* __restrict__ bias)
{
    __shared__ float As[16][68], Bs[16][68];
    int bm=blockIdx.y*64, bn=blockIdx.x*64, t=threadIdx.x;
    int tx=t&15, ty=t>>4;
    float acc[4][4];
#pragma unroll
    for(int i=0;i<4;i++)
#pragma unroll
    for(int j=0;j<4;j++) acc[i][j]=0.f;
    for(int k0=0;k0<K;k0+=16){
#pragma unroll
        for(int i=0;i<4;i++){
            int idx=t+i*256, r=idx>>4, kk=idx&15;
            As[kk][r] = (bm+r<M)? A[(long)(bm+r)*lda+k0+kk] : 0.f;
        }
#pragma unroll
        for(int i=0;i<4;i++){
            int idx=t+i*256, kk=idx>>6, cc=idx&63;
            Bs[kk][cc] = (bn+cc<N)? B[(long)(k0+kk)*ldb+bn+cc] : 0.f;
        }
        __syncthreads();
#pragma unroll
        for(int kk=0;kk<16;kk++){
            float ra[4],rb[4];
#pragma unroll
            for(int i=0;i<4;i++) ra[i]=As[kk][ty*4+i];
#pragma unroll
            for(int j=0;j<4;j++) rb[j]=Bs[kk][tx*4+j];
#pragma unroll
            for(int i=0;i<4;i++)
#pragma unroll
            for(int j=0;j<4;j++) acc[i][j]+=ra[i]*rb[j];
        }
        __syncthreads();
    }
#pragma unroll
    for(int i=0;i<4;i++){
        int gr=bm+ty*4+i; if(gr>=M) continue;
#pragma unroll
        for(int j=0;j<4;j++){
            int gc=bn+tx*4+j; if(gc>=N) continue;
            float v=acc[i][j];
            if(bias) v+=bias[gc];
            if(ACT==ACT_SILU) v=v/(1.f+expf(-v));
            C[(long)gr*ldc+gc]=v;
        }
    }
}

// ---- LayerNorm D=1024 -> split or fp32 ----
template<bool AFFINE,bool SPLIT>
__global__ void __launch_bounds__(256) ln_k(const float* __restrict__ x,
    float* __restrict__ y, bf* __restrict__ yH, bf* __restrict__ yL,
    const float* __restrict__ g, const float* __restrict__ b)
{
    long row=blockIdx.x; const float* xr=x+row*D_; int t=threadIdx.x;
    float v[4], s=0.f;
#pragma unroll
    for(int i=0;i<4;i++){ v[i]=xr[t+i*256]; s+=v[i]; }
    __shared__ float red[256];
    red[t]=s; __syncthreads();
    for(int o=128;o>0;o>>=1){ if(t<o) red[t]+=red[t+o]; __syncthreads(); }
    float m=red[0]*(1.f/D_); __syncthreads();
    float vs=0.f;
#pragma unroll
    for(int i=0;i<4;i++){ float d=v[i]-m; vs+=d*d; }
    red[t]=vs; __syncthreads();
    for(int o=128;o>0;o>>=1){ if(t<o) red[t]+=red[t+o]; __syncthreads(); }
    float rs=1.f/sqrtf(red[0]*(1.f/D_)+1e-5f);
#pragma unroll
    for(int i=0;i<4;i++){
        int c=t+i*256; float o=(v[i]-m)*rs;
        if(AFFINE) o=o*g[c]+b[c];
        if(SPLIT){ bf h,l; sp2(o,h,l); yH[row*D_+c]=h; yL[row*D_+c]=l; }
        else y[row*D_+c]=o;
    }
}

// ---- softmax 1024 -> split ----
__global__ void __launch_bounds__(256) softmax_k(const float* __restrict__ x,
    bf* __restrict__ pH, bf* __restrict__ pL)
{
    long row=blockIdx.x; const float* p=x+row*N1_; int t=threadIdx.x;
    float v[4], mx=-1e30f;
#pragma unroll
    for(int i=0;i<4;i++){ v[i]=p[t+i*256]; mx=fmaxf(mx,v[i]); }
    __shared__ float red[256];
    red[t]=mx; __syncthreads();
    for(int o=128;o>0;o>>=1){ if(t<o) red[t]=fmaxf(red[t],red[t+o]); __syncthreads(); }
    mx=red[0]; __syncthreads();
    float s=0.f;
#pragma unroll
    for(int i=0;i<4;i++){ v[i]=expf(v[i]-mx); s+=v[i]; }
    red[t]=s; __syncthreads();
    for(int o=128;o>0;o>>=1){ if(t<o) red[t]+=red[t+o]; __syncthreads(); }
    float inv=1.f/red[0];
#pragma unroll
    for(int i=0;i<4;i++){
        int c=t+i*256; bf h,l; sp2(v[i]*inv,h,l);
        pH[row*N1_+c]=h; pL[row*N1_+c]=l;
    }
}

// ---- split fp32 -> hi/lo; GELU variant ----
__global__ void split_k(const float* __restrict__ s, bf* __restrict__ h, bf* __restrict__ l, int n)
{
    int i=blockIdx.x*blockDim.x+threadIdx.x;
    if(i>=n) return;
    bf hh,ll; sp2(s[i],hh,ll); h[i]=hh; l[i]=ll;
}
__global__ void gsplit_k(const float* __restrict__ s, bf* __restrict__ h, bf* __restrict__ l, int n)
{
    int i=blockIdx.x*blockDim.x+threadIdx.x;
    if(i>=n) return;
    float v=s[i];
    v = 0.5f*v*(1.f+erff(v*0.70710678118654752f));
    bf hh,ll; sp2(v,hh,ll); h[i]=hh; l[i]=ll;
}

// ---- transpose+split fp32 [K][N] -> pairs [N][K], z-batched ----
__global__ void wsplitT(const float* __restrict__ src, bf* __restrict__ th, bf* __restrict__ tl,
                        int K,int N,long sz)
{
    __shared__ float tile[32][33];
    int z=blockIdx.z;
    const float* S=src+(long)z*sz;
    bf* TH=th+(long)z*sz; bf* TL=tl+(long)z*sz;
    int n0=blockIdx.x*32, k0=blockIdx.y*32;
    int tx=threadIdx.x, ty=threadIdx.y;
#pragma unroll
    for(int j=0;j<4;j++){
        int k=k0+ty+j*8;
        tile[ty+j*8][tx] = (k<K && n0+tx<N)? S[(long)k*N+n0+tx] : 0.f;
    }
    __syncthreads();
#pragma unroll
    for(int j=0;j<4;j++){
        int n=n0+ty+j*8, k=k0+tx;
        if(n<N && k<K){ bf h,l; sp2(tile[tx][ty+j*8],h,l);
            TH[(long)n*K+k]=h; TL[(long)n*K+k]=l; }
    }
}

// ---- transpose bf16 pairs [R][C] -> [C][R], z-batched ----
__global__ void btransp(const bf* __restrict__ ih,const bf* __restrict__ il,
                        bf* __restrict__ oh, bf* __restrict__ ol,int R,int C)
{
    __shared__ bf th[32][33], tl[32][33];
    long zo=(long)blockIdx.z*R*C;
    int c0=blockIdx.x*32, r0=blockIdx.y*32;
    int tx=threadIdx.x, ty=threadIdx.y;
#pragma unroll
    for(int j=0;j<4;j++){
        int r=r0+ty+j*8;
        th[ty+j*8][tx]=ih[zo+(long)r*C+c0+tx];
        tl[ty+j*8][tx]=il[zo+(long)r*C+c0+tx];
    }
    __syncthreads();
#pragma unroll
    for(int j=0;j<4;j++){
        int c=c0+ty+j*8, r=r0+tx;
        oh[zo+(long)c*R+r]=th[tx][ty+j*8];
        ol[zo+(long)c*R+r]=tl[tx][ty+j*8];
    }
}

// ---- misc ----
__global__ void timestep_k(const float* __restrict__ ts, float* __restrict__ out){
    int b=blockIdx.x,i=threadIdx.x;
    int j=(i<160)?i:(i-160);
    float f=expf(-logf(10000.f)*(float)j/160.f);
    double a=(double)(ts[b]*f);
    out[b*TD_+i]=(i<160)?(float)cos(a):(float)sin(a);
}
__global__ void silu_split_k(const float* __restrict__ x,float* __restrict__ y,
                             bf* __restrict__ yH,bf* __restrict__ yL,int n){
    int i=blockIdx.x*blockDim.x+threadIdx.x;
    if(i<n){ float v=x[i]; v=v/(1.f+expf(-v)); y[i]=v;
        bf h,l; sp2(v,h,l); yH[i]=h; yL[i]=l; }
}
__global__ void bcast_k(const float* __restrict__ s,float* __restrict__ d,int n,int per){
    int i=blockIdx.x*blockDim.x+threadIdx.x;
    if(i<n) d[i]=s[i%per];
}
__global__ void modulate_k(const float* __restrict__ q,const float* __restrict__ ada,int loff,
                           bf* __restrict__ qH,bf* __restrict__ qL){
    int i=blockIdx.x*blockDim.x+threadIdx.x;
    if(i>=BS_*NQ_*D_) return;
    int b=i/(NQ_*D_), c=i&(D_-1);
    const float* ap=ada+(long)b*ADAW+loff;
    float v=q[i]*(1.f+ap[2*D_+c])+ap[c];
    bf h,l; sp2(v,h,l); qH[i]=h; qL[i]=l;
}
__global__ void zero_k(float* __restrict__ p,int n){
    int i=blockIdx.x*blockDim.x+threadIdx.x;
    if(i<n) p[i]=0.f;
}

// ---- host ----
#define GSA(p,s) cudaGetSymbolAddress((void**)&p,s)
static inline dim3 tg(int M,int N,int z){ return dim3((unsigned)((N+127)/128),(unsigned)((M+127)/128),(unsigned)z); }
#define SMB 81920
static bf* NB_=nullptr;

extern "C" void kernel_launch(void* const* d_in, const int* in_sizes, int n_in,
                              void* d_out, int out_size)
{
    const float *in_x=(const float*)d_in[0], *in_ts=(const float*)d_in[1], *in_lat=(const float*)d_in[2];
    const float *te_w1=(const float*)d_in[3], *te_b1=(const float*)d_in[4];
    const float *te_w2=(const float*)d_in[5], *te_b2=(const float*)d_in[6];
    const float *pin_w=(const float*)d_in[7], *pin_b=(const float*)d_in[8];
    const float *ln1_g=(const float*)d_in[9], *ln1_b=(const float*)d_in[10];
    const float *ln2_g=(const float*)d_in[11], *ln2_b=(const float*)d_in[12];
    const float *wq=(const float*)d_in[13], *wkv=(const float*)d_in[14], *wo=(const float*)d_in[15];
    const float *flg=(const float*)d_in[16], *flb=(const float*)d_in[17];
    const float *fw1=(const float*)d_in[18], *fw2=(const float*)d_in[19];
    const float *aw=(const float*)d_in[20], *ab=(const float*)d_in[21];
    const float *pout_w=(const float*)d_in[22], *pout_b=(const float*)d_in[23];
    const float *ng=(const float*)d_in[24], *nb=(const float*)d_in[25];
    float* out=(float*)d_out;

    cudaFuncSetAttribute(mgemm<CM_STORE>,cudaFuncAttributeMaxDynamicSharedMemorySize,SMB);
    cudaFuncSetAttribute(mgemm<CM_ATOM>, cudaFuncAttributeMaxDynamicSharedMemorySize,SMB);
    cudaFuncSetAttribute(mgemm<CM_SPLIT>,cudaFuncAttributeMaxDynamicSharedMemorySize,SMB);

    float *xp,*temb0,*temb1,*temb,*stemb,*ada,*lat,*q,*att,*vout,*hff,*h1;
    GSA(xp,g_xp); GSA(temb0,g_temb0); GSA(temb1,g_temb1); GSA(temb,g_temb);
    GSA(stemb,g_stemb); GSA(ada,g_ada); GSA(lat,g_lat); GSA(q,g_q);
    GSA(att,g_att); GSA(vout,g_vout); GSA(hff,g_hff); GSA(h1,g_h1);
    bf *inxH,*inxL,*pinH,*pinL,*xnH,*xnL,*xnTH,*xnTL,*latnH,*latnL,*qH,*qL,*qpH,*qpL;
    bf *attH,*attL,*ovH,*ovL,*voH,*voL,*hffH,*hffL,*h1H,*h1L,*latH,*latL,*stH,*stL;
    bf *wqH,*wqL,*kvH,*kvL,*kvTH,*kvTL,*woH,*woL,*f1H,*f1L,*f2H,*f2L,*awH,*awL,*poH,*poL;
    GSA(inxH,s_inxH); GSA(inxL,s_inxL); GSA(pinH,s_pinH); GSA(pinL,s_pinL);
    GSA(xnH,s_xnH); GSA(xnL,s_xnL); GSA(xnTH,s_xnTH); GSA(xnTL,s_xnTL);
    GSA(latnH,s_latnH); GSA(latnL,s_latnL); GSA(qH,s_qH); GSA(qL,s_qL);
    GSA(qpH,s_qpH); GSA(qpL,s_qpL); GSA(attH,s_attH); GSA(attL,s_attL);
    GSA(ovH,s_ovH); GSA(ovL,s_ovL); GSA(voH,s_voH); GSA(voL,s_voL);
    GSA(hffH,s_hffH); GSA(hffL,s_hffL); GSA(h1H,s_h1H); GSA(h1L,s_h1L);
    GSA(latH,s_latH); GSA(latL,s_latL); GSA(stH,s_stH); GSA(stL,s_stL);
    GSA(wqH,s_wqH); GSA(wqL,s_wqL); GSA(kvH,s_kvH); GSA(kvL,s_kvL);
    GSA(kvTH,s_kvTH); GSA(kvTL,s_kvTL); GSA(woH,s_woH); GSA(woL,s_woL);
    GSA(f1H,s_f1H); GSA(f1L,s_f1L); GSA(f2H,s_f2H); GSA(f2L,s_f2L);
    GSA(awH,s_awH); GSA(awL,s_awL); GSA(poH,s_poH); GSA(poL,s_poL);

    dim3 t32(32,8);
    // ---- weight prep ----
    wsplitT<<<dim3(D_/32,ED_/32,1),t32>>>(pin_w,pinH,pinL,ED_,D_,0);
    wsplitT<<<dim3(INNER/32,D_/32,DEPTH),t32>>>(wq,wqH,wqL,D_,INNER,(long)D_*INNER);
    split_k<<<(DEPTH*D_*2*INNER+255)/256,256>>>(wkv,kvH,kvL,DEPTH*D_*2*INNER);
    wsplitT<<<dim3(2*INNER/32,D_/32,DEPTH),t32>>>(wkv,kvTH,kvTL,D_,2*INNER,(long)D_*2*INNER);
    wsplitT<<<dim3(D_/32,INNER/32,DEPTH),t32>>>(wo,woH,woL,INNER,D_,(long)INNER*D_);
    wsplitT<<<dim3(FF_/32,D_/32,DEPTH),t32>>>(fw1,f1H,f1L,D_,FF_,(long)D_*FF_);
    wsplitT<<<dim3(D_/32,FF_/32,DEPTH),t32>>>(fw2,f2H,f2L,FF_,D_,(long)FF_*D_);
    wsplitT<<<dim3(4*D_/32,D_/32,DEPTH),t32>>>(aw,awH,awL,D_,4*D_,(long)D_*4*D_);
    wsplitT<<<dim3(D_/32,D_/32,1),t32>>>(pout_w,poH,poL,D_,D_,0);
    split_k<<<(BS_*N1_*ED_+255)/256,256>>>(in_x,inxH,inxL,BS_*N1_*ED_);

    // ---- timestep embedding ----
    timestep_k<<<BS_,TD_>>>(in_ts,temb0);
    gemm_s<ACT_SILU><<<dim3(16,1),256>>>(BS_,D_,TD_,temb0,TD_,te_w1,D_,temb1,D_,te_b1);
    gemm_s<ACT_NONE><<<dim3(16,1),256>>>(BS_,D_,D_,temb1,D_,te_w2,D_,temb,D_,te_b2);
    silu_split_k<<<(BS_*D_+255)/256,256>>>(temb,stemb,stH,stL,BS_*D_);

    // ---- batched adaLN for ALL layers: ada[b, l*4D+c] = silu(temb) @ aw_l + ab_l ----
    mgemm<CM_STORE><<<tg(BS_,DEPTH*4*D_,1),256,SMB>>>(
        BS_,DEPTH*4*D_,D_,1, stH,stL,D_,0, awH,awL,D_,0,
        ada,NB_,NB_,ADAW,0, ab,nullptr,1.f);

    // ---- proj_in + layer-invariant LN + transpose ----
    mgemm<CM_STORE><<<tg(BS_*N1_,D_,1),256,SMB>>>(
        BS_*N1_,D_,ED_,1, inxH,inxL,ED_,0, pinH,pinL,ED_,0,
        xp,NB_,NB_,D_,0, pin_b,nullptr,1.f);
    ln_k<false,true><<<BS_*N1_,256>>>(xp,nullptr,xnH,xnL,nullptr,nullptr);
    btransp<<<dim3(D_/32,N1_/32,BS_),t32>>>(xnH,xnL,xnTH,xnTL,N1_,D_);
    bcast_k<<<(BS_*NQ_*D_+255)/256,256>>>(in_lat,lat,BS_*NQ_*D_,NQ_*D_);

    for(int l=0;l<DEPTH;l++){
        const float *g1=ln1_g+l*D_, *b1=ln1_b+l*D_, *g2=ln2_g+l*D_, *b2=ln2_b+l*D_;
        const float *fg=flg+l*D_, *fb=flb+l*D_;
        const bf *wqh=wqH+(long)l*INNER*D_, *wql=wqL+(long)l*INNER*D_;
        const bf *kvh=kvH+(long)l*D_*2*INNER, *kvl=kvL+(long)l*D_*2*INNER;
        const bf *kvth=kvTH+(long)l*2*INNER*D_, *kvtl=kvTL+(long)l*2*INNER*D_;
        const bf *woh=woH+(long)l*D_*INNER, *wol=woL+(long)l*D_*INNER;
        const bf *f1h=f1H+(long)l*FF_*D_, *f1l=f1L+(long)l*FF_*D_;
        const bf *f2h=f2H+(long)l*D_*FF_, *f2l=f2L+(long)l*D_*FF_;

        // latn -> q (split-K=8) -> modulate+split
        ln_k<true,true><<<BS_*NQ_,256>>>(lat,nullptr,latnH,latnL,g2,b2);
        zero_k<<<(BS_*NQ_*D_+255)/256,256>>>(q,BS_*NQ_*D_);
        mgemm<CM_ATOM><<<tg(BS_*NQ_,INNER,8),256,SMB>>>(
            BS_*NQ_,INNER,D_,8, latnH,latnL,D_,0, wqh,wql,D_,0,
            q,NB_,NB_,INNER,0, nullptr,nullptr,1.f);
        modulate_k<<<(BS_*NQ_*D_+255)/256,256>>>(q,ada,l*4*D_,qH,qL);

        // qp(split out, ⊙g1) = SCALE * qmod_h @ wk_h^T (z=heads)
        mgemm<CM_SPLIT><<<tg(BS_*NQ_,D_,H_),256,SMB>>>(
            BS_*NQ_,D_,DH_,1, qH,qL,INNER,64, kvh,kvl,2*INNER,64,
            nullptr,qpH,qpL,H_*D_,(long)D_, nullptr,g1,SCALE_);

        // logits = qp' @ xn^T (z=batch); b1 drops (softmax shift-invariance)
        mgemm<CM_STORE><<<tg(NQ_*H_,N1_,BS_),256,SMB>>>(
            NQ_*H_,N1_,D_,1, qpH,qpL,D_,(long)NQ_*H_*D_, xnH,xnL,D_,(long)N1_*D_,
            att,NB_,NB_,N1_,(long)NQ_*H_*N1_, nullptr,nullptr,1.f);
        softmax_k<<<BS_*NQ_*H_,256>>>(att,attH,attL);

        // ov(split out, g1*x+b1) = attn @ xn (z=batch, via xnT)
        mgemm<CM_SPLIT><<<tg(NQ_*H_,D_,BS_),256,SMB>>>(
            NQ_*H_,D_,N1_,1, attH,attL,N1_,(long)NQ_*H_*N1_, xnTH,xnTL,N1_,(long)D_*N1_,
            nullptr,ovH,ovL,D_,(long)NQ_*H_*D_, b1,g1,1.f);

        // vout = ovm_h @ wv_h (z=heads, split-K=4)
        zero_k<<<(BS_*NQ_*D_+255)/256,256>>>(vout,BS_*NQ_*D_);
        mgemm<CM_ATOM><<<tg(BS_*NQ_,DH_,H_*4),256,SMB>>>(
            BS_*NQ_,DH_,D_,4, ovH,ovL,H_*D_,(long)D_, kvth+(long)INNER*D_,kvtl+(long)INNER*D_,D_,(long)64*D_,
            vout,NB_,NB_,D_,64, nullptr,nullptr,1.f);
        split_k<<<(BS_*NQ_*D_+255)/256,256>>>(vout,voH,voL,BS_*NQ_*D_);

        // lat += vout @ wo (split-K=8)
        mgemm<CM_ATOM><<<tg(BS_*NQ_,D_,8),256,SMB>>>(
            BS_*NQ_,D_,INNER,8, voH,voL,INNER,0, woh,wol,INNER,0,
            lat,NB_,NB_,D_,0, nullptr,nullptr,1.f);

        // FF: h1 raw (split-K=2) -> GELU+split -> ff2 (split-K=8)
        ln_k<true,true><<<BS_*NQ_,256>>>(lat,nullptr,hffH,hffL,fg,fb);
        zero_k<<<(BS_*NQ_*FF_+255)/256,256>>>(h1,BS_*NQ_*FF_);
        mgemm<CM_ATOM><<<tg(BS_*NQ_,FF_,2),256,SMB>>>(
            BS_*NQ_,FF_,D_,2, hffH,hffL,D_,0, f1h,f1l,D_,0,
            h1,NB_,NB_,FF_,0, nullptr,nullptr,1.f);
        gsplit_k<<<(BS_*NQ_*FF_+255)/256,256>>>(h1,h1H,h1L,BS_*NQ_*FF_);
        mgemm<CM_ATOM><<<tg(BS_*NQ_,D_,8),256,SMB>>>(
            BS_*NQ_,D_,FF_,8, h1H,h1L,FF_,0, f2h,f2l,FF_,0,
            lat,NB_,NB_,D_,0, nullptr,nullptr,1.f);
    }

    // ---- proj_out (split-K=8) + final LN ----
    split_k<<<(BS_*NQ_*D_+255)/256,256>>>(lat,latH,latL,BS_*NQ_*D_);
    zero_k<<<(BS_*NQ_*D_+255)/256,256>>>(hff,BS_*NQ_*D_);
    mgemm<CM_ATOM><<<tg(BS_*NQ_,D_,8),256,SMB>>>(
        BS_*NQ_,D_,D_,8, latH,latL,D_,0, poH,poL,D_,0,
        hff,NB_,NB_,D_,0, pout_b,nullptr,1.f);
    ln_k<true,false><<<BS_*NQ_,256>>>(hff,out,nullptr,nullptr,ng,nb);
}

// round 8
// speedup vs baseline: 3.7834x; 1.0188x over previous
#include <cuda_runtime.h>
#include <cuda_bf16.h>
#include <math.h>
#include <stdint.h>

#define D_    1024
#define DEPTH 8
#define H_    16
#define DH_   64
#define INNER 1024
#define NQ_   8
#define ED_   768
#define FF_   4096
#define TD_   320
#define BS_   32
#define N1_   1024
#define SCALE_ 0.125f
#define ADAW  32768

#define ACT_NONE 0
#define ACT_SILU 1
#define CM_STORE 0
#define CM_ATOM  1
#define CM_SPLIT 2

typedef __nv_bfloat16 bf;

// ---- fp32 scratch ----
__device__ float g_xp[BS_*N1_*D_];
__device__ float g_temb0[BS_*TD_];
__device__ float g_temb1[BS_*D_];
__device__ float g_temb[BS_*D_];
__device__ float g_stemb[BS_*D_];
__device__ float g_ada[BS_*ADAW];
__device__ float g_lat[BS_*NQ_*D_];
__device__ float g_q[BS_*NQ_*D_];
__device__ float g_att[BS_*NQ_*H_*N1_];
__device__ float g_vout[BS_*NQ_*D_];
__device__ float g_hff[BS_*NQ_*D_];
__device__ float g_h1[BS_*NQ_*FF_];

// ---- bf16 hi/lo pairs ----
__device__ bf s_inxH[BS_*N1_*ED_],  s_inxL[BS_*N1_*ED_];
__device__ bf s_pinH[D_*ED_],       s_pinL[D_*ED_];
__device__ bf s_xnH[BS_*N1_*D_],    s_xnL[BS_*N1_*D_];
__device__ bf s_xnTH[BS_*D_*N1_],   s_xnTL[BS_*D_*N1_];
__device__ bf s_latnH[BS_*NQ_*D_],  s_latnL[BS_*NQ_*D_];
__device__ bf s_qH[BS_*NQ_*D_],     s_qL[BS_*NQ_*D_];
__device__ bf s_qpH[BS_*NQ_*H_*D_], s_qpL[BS_*NQ_*H_*D_];
__device__ bf s_attH[BS_*NQ_*H_*N1_], s_attL[BS_*NQ_*H_*N1_];
__device__ bf s_ovH[BS_*NQ_*H_*D_], s_ovL[BS_*NQ_*H_*D_];
__device__ bf s_voH[BS_*NQ_*D_],    s_voL[BS_*NQ_*D_];
__device__ bf s_hffH[BS_*NQ_*D_],   s_hffL[BS_*NQ_*D_];
__device__ bf s_h1H[BS_*NQ_*FF_],   s_h1L[BS_*NQ_*FF_];
__device__ bf s_latH[BS_*NQ_*D_],   s_latL[BS_*NQ_*D_];
__device__ bf s_stH[BS_*D_],        s_stL[BS_*D_];
__device__ bf s_wqH[DEPTH*INNER*D_],  s_wqL[DEPTH*INNER*D_];
__device__ bf s_kvH[DEPTH*D_*2*INNER],s_kvL[DEPTH*D_*2*INNER];
__device__ bf s_kvTH[DEPTH*2*INNER*D_],s_kvTL[DEPTH*2*INNER*D_];
__device__ bf s_woH[DEPTH*D_*INNER],  s_woL[DEPTH*D_*INNER];
__device__ bf s_f1H[DEPTH*FF_*D_],    s_f1L[DEPTH*FF_*D_];
__device__ bf s_f2H[DEPTH*D_*FF_],    s_f2L[DEPTH*D_*FF_];
__device__ bf s_awH[DEPTH*4*D_*D_],   s_awL[DEPTH*4*D_*D_];
__device__ bf s_poH[D_*D_],           s_poL[D_*D_];

// ---- helpers ----
__device__ __forceinline__ uint32_t smem_u32(const void* p){
    uint32_t a;
    asm("{ .reg .u64 t; cvta.to.shared.u64 t, %1; cvt.u32.u64 %0, t; }":"=r"(a):"l"(p));
    return a;
}
__device__ __forceinline__ void sp2(float v, bf& h, bf& l){
    h = __float2bfloat16_rn(v);
    l = __float2bfloat16_rn(v - __bfloat162float(h));
}
#define CPA(d,s) asm volatile("cp.async.cg.shared.global [%0],[%1],16;"::"r"(d),"l"(s):"memory")
#define CPC()    asm volatile("cp.async.commit_group;":::"memory")
#define CPW(n)   asm volatile("cp.async.wait_group %0;"::"n"(n):"memory")
#define LDSM4(r,a) asm volatile("ldmatrix.sync.aligned.m8n8.x4.shared.b16 {%0,%1,%2,%3},[%4];" \
    :"=r"((r)[0]),"=r"((r)[1]),"=r"((r)[2]),"=r"((r)[3]):"r"(a))
#define MMA(d,a,b) asm volatile("mma.sync.aligned.m16n8k16.row.col.f32.bf16.bf16.f32 " \
    "{%0,%1,%2,%3},{%4,%5,%6,%7},{%8,%9},{%0,%1,%2,%3};" \
    :"+f"((d)[0]),"+f"((d)[1]),"+f"((d)[2]),"+f"((d)[3]) \
    :"r"((a)[0]),"r"((a)[1]),"r"((a)[2]),"r"((a)[3]),"r"((b)[0]),"r"((b)[1]))

// ---- bf16 tensor GEMM: C = A@B^T (3-pass hi/lo); fp32 store/atom or split-pair out ----
template<int CMODE>
__global__ void __launch_bounds__(256,2) mgemm(
    int M,int N,int K,int ksplit,
    const bf* __restrict__ Ah,const bf* __restrict__ Al,int lda,long sAz,
    const bf* __restrict__ Bh,const bf* __restrict__ Bl,int ldb,long sBz,
    float* __restrict__ C, bf* __restrict__ CH, bf* __restrict__ CL, int ldc, long sCz,
    const float* __restrict__ bias, const float* __restrict__ cscale, float alpha)
{
    extern __shared__ bf sh[];
    const int t=threadIdx.x, lane=t&31, wid=t>>5;
    const int zz=blockIdx.z, batch=zz/ksplit, kp=zz-batch*ksplit;
    const int Kl=K/ksplit, koff=kp*Kl, NC=Kl>>5;
    const int bm=blockIdx.y*128, bn=blockIdx.x*128;
    Ah+=(long)batch*sAz; Al+=(long)batch*sAz;
    Bh+=(long)batch*sBz; Bl+=(long)batch*sBz;
    const uint32_t sb = smem_u32(sh);
    const int mw=(wid>>2)*64, nw=(wid&3)*32;

    float acc[4][4][4];
#pragma unroll
    for(int a=0;a<4;a++)
#pragma unroll
    for(int b=0;b<4;b++)
#pragma unroll
    for(int c=0;c<4;c++) acc[a][b][c]=0.f;

    auto fill=[&](int st,int c){
#pragma unroll
        for(int i=0;i<2;i++){
            int f=t+i*256, row=f>>2, ch=(f&3)*8;
            long ao=(long)(bm+row)*lda + koff + c*32 + ch;
            uint32_t d0 = sb + st*40960u + (uint32_t)(row*40+ch)*2u;
            CPA(d0,       Ah+ao);
            CPA(d0+10240, Al+ao);
            int rn=bn+row; if(rn>=N) rn=N-1;
            long bo=(long)rn*ldb + koff + c*32 + ch;
            CPA(d0+20480, Bh+bo);
            CPA(d0+30720, Bl+bo);
        }
        CPC();
    };

    fill(0,0);
    for(int c=0;c<NC;c++){
        int st=c&1;
        if(c+1<NC){ fill(st^1,c+1); CPW(1); } else { CPW(0); }
        __syncthreads();
        uint32_t base = sb + st*40960u;
#pragma unroll
        for(int ks=0;ks<2;ks++){
            uint32_t kadd = (uint32_t)(ks*32 + (lane>>4)*16);
            uint32_t Af[4][4], Bh2[4][2], Bl2[4][2];
#pragma unroll
            for(int mt=0;mt<4;mt++)
                LDSM4(Af[mt], base + (uint32_t)(mw+mt*16+(lane&15))*80u + kadd);
#pragma unroll
            for(int np=0;np<2;np++){
                uint32_t qq[4];
                LDSM4(qq, base+20480u + (uint32_t)(nw+np*16+(lane&15))*80u + kadd);
                Bh2[np*2][0]=qq[0]; Bh2[np*2][1]=qq[2];
                Bh2[np*2+1][0]=qq[1]; Bh2[np*2+1][1]=qq[3];
            }
#pragma unroll
            for(int mt=0;mt<4;mt++)
#pragma unroll
            for(int nt=0;nt<4;nt++) MMA(acc[mt][nt],Af[mt],Bh2[nt]);
#pragma unroll
            for(int np=0;np<2;np++){
                uint32_t qq[4];
                LDSM4(qq, base+30720u + (uint32_t)(nw+np*16+(lane&15))*80u + kadd);
                Bl2[np*2][0]=qq[0]; Bl2[np*2][1]=qq[2];
                Bl2[np*2+1][0]=qq[1]; Bl2[np*2+1][1]=qq[3];
            }
#pragma unroll
            for(int mt=0;mt<4;mt++)
#pragma unroll
            for(int nt=0;nt<4;nt++) MMA(acc[mt][nt],Af[mt],Bl2[nt]);
#pragma unroll
            for(int mt=0;mt<4;mt++)
                LDSM4(Af[mt], base+10240u + (uint32_t)(mw+mt*16+(lane&15))*80u + kadd);
#pragma unroll
            for(int mt=0;mt<4;mt++)
#pragma unroll
            for(int nt=0;nt<4;nt++) MMA(acc[mt][nt],Af[mt],Bh2[nt]);
        }
        __syncthreads();
    }

    const bool dob = bias && (CMODE!=CM_ATOM || kp==0);
#pragma unroll
    for(int mt=0;mt<4;mt++)
#pragma unroll
    for(int nt=0;nt<4;nt++){
        int gc = bn+nw+nt*8+(lane&3)*2;
#pragma unroll
        for(int rr=0;rr<2;rr++){
            int gr = bm+mw+mt*16+(lane>>2)+rr*8;
            if(gr>=M) continue;
#pragma unroll
            for(int cc=0;cc<2;cc++){
                int c2=gc+cc;
                if(c2>=N) continue;
                float v = acc[mt][nt][rr*2+cc]*alpha;
                if(cscale) v *= cscale[c2];
                if(dob) v += bias[c2];
                long off=(long)batch*sCz + (long)gr*ldc + c2;
                if(CMODE==CM_ATOM) atomicAdd(&C[off],v);
                else if(CMODE==CM_STORE) C[off]=v;
                else { bf h,l; sp2(v,h,l); CH[off]=h; CL[off]=l; }
            }
        }
    }
}

// ---- BM=32 tensor GEMM (M must be exactly 32): C[32,N] = A@B^T + bias ----
#define SM32S 25600
__global__ void __launch_bounds__(256,2) mgemm32(
    int N,int K,
    const bf* __restrict__ Ah,const bf* __restrict__ Al,int lda,
    const bf* __restrict__ Bh,const bf* __restrict__ Bl,int ldb,
    float* __restrict__ C,int ldc,const float* __restrict__ bias)
{
    extern __shared__ bf sh[];
    const int t=threadIdx.x, lane=t&31, wid=t>>5;
    const int bn=blockIdx.x*128;
    const uint32_t sb=smem_u32(sh);
    const int NC=K>>5;
    float acc[2][2][4];
#pragma unroll
    for(int a=0;a<2;a++)
#pragma unroll
    for(int b=0;b<2;b++)
#pragma unroll
    for(int c=0;c<4;c++) acc[a][b][c]=0.f;

    auto fill=[&](int st,int c){
        uint32_t bs=sb+(uint32_t)st*SM32S;
        {
            int row=(t&127)>>2, ch=(t&3)*8;
            const bf* Ap=(t<128)?Ah:Al;
            uint32_t off=(t<128)?0u:2560u;
            CPA(bs+off+(uint32_t)(row*80+ch*2), Ap+(long)row*lda+c*32+ch);
        }
#pragma unroll
        for(int i=0;i<2;i++){
            int f=t+i*256, row=f>>2, ch=(f&3)*8;
            int rn=bn+row; if(rn>=N) rn=N-1;
            long bo=(long)rn*ldb+c*32+ch;
            CPA(bs+5120u+(uint32_t)(row*80+ch*2), Bh+bo);
            CPA(bs+15360u+(uint32_t)(row*80+ch*2), Bl+bo);
        }
        CPC();
    };

    fill(0,0);
    for(int c=0;c<NC;c++){
        int st=c&1;
        if(c+1<NC){ fill(st^1,c+1); CPW(1); } else { CPW(0); }
        __syncthreads();
        uint32_t base=sb+(uint32_t)st*SM32S;
#pragma unroll
        for(int ks=0;ks<2;ks++){
            uint32_t kadd=(uint32_t)(ks*32+(lane>>4)*16);
            uint32_t Af[2][4], Bf[2][2], Bl2[2][2];
#pragma unroll
            for(int mt=0;mt<2;mt++)
                LDSM4(Af[mt], base + (uint32_t)((mt*16+(lane&15))*80) + kadd);
            {
                uint32_t qq[4];
                LDSM4(qq, base+5120u + (uint32_t)((wid*16+(lane&15))*80) + kadd);
                Bf[0][0]=qq[0];Bf[0][1]=qq[2];Bf[1][0]=qq[1];Bf[1][1]=qq[3];
            }
#pragma unroll
            for(int mt=0;mt<2;mt++)
#pragma unroll
            for(int nt=0;nt<2;nt++) MMA(acc[mt][nt],Af[mt],Bf[nt]);
            {
                uint32_t qq[4];
                LDSM4(qq, base+15360u + (uint32_t)((wid*16+(lane&15))*80) + kadd);
                Bl2[0][0]=qq[0];Bl2[0][1]=qq[2];Bl2[1][0]=qq[1];Bl2[1][1]=qq[3];
            }
#pragma unroll
            for(int mt=0;mt<2;mt++)
#pragma unroll
            for(int nt=0;nt<2;nt++) MMA(acc[mt][nt],Af[mt],Bl2[nt]);
#pragma unroll
            for(int mt=0;mt<2;mt++)
                LDSM4(Af[mt], base+2560u + (uint32_t)((mt*16+(lane&15))*80) + kadd);
#pragma unroll
            for(int mt=0;mt<2;mt++)
#pragma unroll
            for(int nt=0;nt<2;nt++) MMA(acc[mt][nt],Af[mt],Bf[nt]);
        }
        __syncthreads();
    }
#pragma unroll
    for(int mt=0;mt<2;mt++)
#pragma unroll
    for(int nt=0;nt<2;nt++){
        int gc=bn+wid*16+nt*8+(lane&3)*2;
#pragma unroll
        for(int rr=0;rr<2;rr++){
            int gr=mt*16+(lane>>2)+rr*8;
#pragma unroll
            for(int cc=0;cc<2;cc++){
                int c2=gc+cc;
                if(c2>=N) continue;
                float v=acc[mt][nt][rr*2+cc];
                if(bias) v+=bias[c2];
                C[(long)gr*ldc+c2]=v;
            }
        }
    }
}

// ---- unified prep: transposes ([K][N]->[N][K] pairs) + plain splits, one launch ----
#define NSEG 10
struct Segs {
    const float* src[NSEG]; bf* dh[NSEG]; bf* dl[NSEG];
    int K[NSEG], N[NSEG], mode[NSEG];
    int bstart[NSEG+1]; int nseg;
};
__global__ void prep_all(Segs S)
{
    __shared__ float tile[32][33];
    int b=blockIdx.x;
    int si=0;
    while(si+1<S.nseg && b>=S.bstart[si+1]) si++;
    int lb=b-S.bstart[si];
    int tx=threadIdx.x, ty=threadIdx.y;
    if(S.mode[si]==0){
        int K=S.K[si], N=S.N[si];
        int tpz=(N/32)*(K/32);
        int z=lb/tpz, rem=lb-z*tpz;
        int n0=(rem%(N/32))*32, k0=(rem/(N/32))*32;
        long zo=(long)z*K*N;
        const float* Sp=S.src[si]+zo; bf* TH=S.dh[si]+zo; bf* TL=S.dl[si]+zo;
#pragma unroll
        for(int j=0;j<4;j++)
            tile[ty+j*8][tx]=Sp[(long)(k0+ty+j*8)*N+n0+tx];
        __syncthreads();
#pragma unroll
        for(int j=0;j<4;j++){
            int n=n0+ty+j*8, k=k0+tx;
            bf h,l; sp2(tile[tx][ty+j*8],h,l);
            TH[(long)n*K+k]=h; TL[(long)n*K+k]=l;
        }
    } else {
        long n=(long)S.K[si];
        long i0=(long)lb*2048 + ty*32+tx;
#pragma unroll
        for(int j=0;j<8;j++){
            long i=i0+j*256;
            if(i<n){ bf h,l; sp2(S.src[si][i],h,l); S.dh[si][i]=h; S.dl[si][i]=l; }
        }
    }
}

// ---- SIMT fp32 GEMM (temb only) ----
template<int ACT>
__global__ void __launch_bounds__(256) gemm_s(
    int M,int N,int K,
    const float* __restrict__ A,int lda,
    const float* __restrict__ B,int ldb,
    float* __restrict__ C,int ldc,
    const float* __restrict__ bias)
{
    __shared__ float As[16][68], Bs[16][68];
    int bm=blockIdx.y*64, bn=blockIdx.x*64, t=threadIdx.x;
    int tx=t&15, ty=t>>4;
    float acc[4][4];
#pragma unroll
    for(int i=0;i<4;i++)
#pragma unroll
    for(int j=0;j<4;j++) acc[i][j]=0.f;
    for(int k0=0;k0<K;k0+=16){
#pragma unroll
        for(int i=0;i<4;i++){
            int idx=t+i*256, r=idx>>4, kk=idx&15;
            As[kk][r] = (bm+r<M)? A[(long)(bm+r)*lda+k0+kk] : 0.f;
        }
#pragma unroll
        for(int i=0;i<4;i++){
            int idx=t+i*256, kk=idx>>6, cc=idx&63;
            Bs[kk][cc] = (bn+cc<N)? B[(long)(k0+kk)*ldb+bn+cc] : 0.f;
        }
        __syncthreads();
#pragma unroll
        for(int kk=0;kk<16;kk++){
            float ra[4],rb[4];
#pragma unroll
            for(int i=0;i<4;i++) ra[i]=As[kk][ty*4+i];
#pragma unroll
            for(int j=0;j<4;j++) rb[j]=Bs[kk][tx*4+j];
#pragma unroll
            for(int i=0;i<4;i++)
#pragma unroll
            for(int j=0;j<4;j++) acc[i][j]+=ra[i]*rb[j];
        }
        __syncthreads();
    }
#pragma unroll
    for(int i=0;i<4;i++){
        int gr=bm+ty*4+i; if(gr>=M) continue;
#pragma unroll
        for(int j=0;j<4;j++){
            int gc=bn+tx*4+j; if(gc>=N) continue;
            float v=acc[i][j];
            if(bias) v+=bias[gc];
            if(ACT==ACT_SILU) v=v/(1.f+expf(-v));
            C[(long)gr*ldc+gc]=v;
        }
    }
}

// ---- LayerNorm D=1024 -> split or fp32 ----
template<bool AFFINE,bool SPLIT>
__global__ void __launch_bounds__(256) ln_k(const float* __restrict__ x,
    float* __restrict__ y, bf* __restrict__ yH, bf* __restrict__ yL,
    const float* __restrict__ g, const float* __restrict__ b)
{
    long row=blockIdx.x; const float* xr=x+row*D_; int t=threadIdx.x;
    float v[4], s=0.f;
#pragma unroll
    for(int i=0;i<4;i++){ v[i]=xr[t+i*256]; s+=v[i]; }
    __shared__ float red[256];
    red[t]=s; __syncthreads();
    for(int o=128;o>0;o>>=1){ if(t<o) red[t]+=red[t+o]; __syncthreads(); }
    float m=red[0]*(1.f/D_); __syncthreads();
    float vs=0.f;
#pragma unroll
    for(int i=0;i<4;i++){ float d=v[i]-m; vs+=d*d; }
    red[t]=vs; __syncthreads();
    for(int o=128;o>0;o>>=1){ if(t<o) red[t]+=red[t+o]; __syncthreads(); }
    float rs=1.f/sqrtf(red[0]*(1.f/D_)+1e-5f);
#pragma unroll
    for(int i=0;i<4;i++){
        int c=t+i*256; float o=(v[i]-m)*rs;
        if(AFFINE) o=o*g[c]+b[c];
        if(SPLIT){ bf h,l; sp2(o,h,l); yH[row*D_+c]=h; yL[row*D_+c]=l; }
        else y[row*D_+c]=o;
    }
}

// ---- softmax 1024 -> split ----
__global__ void __launch_bounds__(256) softmax_k(const float* __restrict__ x,
    bf* __restrict__ pH, bf* __restrict__ pL)
{
    long row=blockIdx.x; const float* p=x+row*N1_; int t=threadIdx.x;
    float v[4], mx=-1e30f;
#pragma unroll
    for(int i=0;i<4;i++){ v[i]=p[t+i*256]; mx=fmaxf(mx,v[i]); }
    __shared__ float red[256];
    red[t]=mx; __syncthreads();
    for(int o=128;o>0;o>>=1){ if(t<o) red[t]=fmaxf(red[t],red[t+o]); __syncthreads(); }
    mx=red[0]; __syncthreads();
    float s=0.f;
#pragma unroll
    for(int i=0;i<4;i++){ v[i]=expf(v[i]-mx); s+=v[i]; }
    red[t]=s; __syncthreads();
    for(int o=128;o>0;o>>=1){ if(t<o) red[t]+=red[t+o]; __syncthreads(); }
    float inv=1.f/red[0];
#pragma unroll
    for(int i=0;i<4;i++){
        int c=t+i*256; bf h,l; sp2(v[i]*inv,h,l);
        pH[row*N1_+c]=h; pL[row*N1_+c]=l;
    }
}

// ---- split / gelu-split ----
__global__ void split_k(const float* __restrict__ s, bf* __restrict__ h, bf* __restrict__ l, int n)
{
    int i=blockIdx.x*blockDim.x+threadIdx.x;
    if(i>=n) return;
    bf hh,ll; sp2(s[i],hh,ll); h[i]=hh; l[i]=ll;
}
__global__ void gsplit_k(const float* __restrict__ s, bf* __restrict__ h, bf* __restrict__ l, int n)
{
    int i=blockIdx.x*blockDim.x+threadIdx.x;
    if(i>=n) return;
    float v=s[i];
    v = 0.5f*v*(1.f+erff(v*0.70710678118654752f));
    bf hh,ll; sp2(v,hh,ll); h[i]=hh; l[i]=ll;
}

// ---- transpose bf16 pairs [R][C] -> [C][R], z-batched ----
__global__ void btransp(const bf* __restrict__ ih,const bf* __restrict__ il,
                        bf* __restrict__ oh, bf* __restrict__ ol,int R,int C)
{
    __shared__ bf th[32][33], tl[32][33];
    long zo=(long)blockIdx.z*R*C;
    int c0=blockIdx.x*32, r0=blockIdx.y*32;
    int tx=threadIdx.x, ty=threadIdx.y;
#pragma unroll
    for(int j=0;j<4;j++){
        int r=r0+ty+j*8;
        th[ty+j*8][tx]=ih[zo+(long)r*C+c0+tx];
        tl[ty+j*8][tx]=il[zo+(long)r*C+c0+tx];
    }
    __syncthreads();
#pragma unroll
    for(int j=0;j<4;j++){
        int c=c0+ty+j*8, r=r0+tx;
        oh[zo+(long)c*R+r]=th[tx][ty+j*8];
        ol[zo+(long)c*R+r]=tl[tx][ty+j*8];
    }
}

// ---- misc ----
__global__ void timestep_k(const float* __restrict__ ts, float* __restrict__ out){
    int b=blockIdx.x,i=threadIdx.x;
    int j=(i<160)?i:(i-160);
    float f=expf(-logf(10000.f)*(float)j/160.f);
    double a=(double)(ts[b]*f);
    out[b*TD_+i]=(i<160)?(float)cos(a):(float)sin(a);
}
__global__ void silu_split_k(const float* __restrict__ x,float* __restrict__ y,
                             bf* __restrict__ yH,bf* __restrict__ yL,int n){
    int i=blockIdx.x*blockDim.x+threadIdx.x;
    if(i<n){ float v=x[i]; v=v/(1.f+expf(-v)); y[i]=v;
        bf h,l; sp2(v,h,l); yH[i]=h; yL[i]=l; }
}
__global__ void bcast_k(const float* __restrict__ s,float* __restrict__ d,int n,int per){
    int i=blockIdx.x*blockDim.x+threadIdx.x;
    if(i<n) d[i]=s[i%per];
}
__global__ void modulate_k(const float* __restrict__ q,const float* __restrict__ ada,int loff,
                           bf* __restrict__ qH,bf* __restrict__ qL){
    int i=blockIdx.x*blockDim.x+threadIdx.x;
    if(i>=BS_*NQ_*D_) return;
    int b=i/(NQ_*D_), c=i&(D_-1);
    const float* ap=ada+(long)b*ADAW+loff;
    float v=q[i]*(1.f+ap[2*D_+c])+ap[c];
    bf h,l; sp2(v,h,l); qH[i]=h; qL[i]=l;
}

// ---- host ----
#define GSA(p,s) cudaGetSymbolAddress((void**)&p,s)
static inline dim3 tg(int M,int N,int z){ return dim3((unsigned)((N+127)/128),(unsigned)((M+127)/128),(unsigned)z); }
#define SMB 81920
static bf* NB_=nullptr;

extern "C" void kernel_launch(void* const* d_in, const int* in_sizes, int n_in,
                              void* d_out, int out_size)
{
    const float *in_x=(const float*)d_in[0], *in_ts=(const float*)d_in[1], *in_lat=(const float*)d_in[2];
    const float *te_w1=(const float*)d_in[3], *te_b1=(const float*)d_in[4];
    const float *te_w2=(const float*)d_in[5], *te_b2=(const float*)d_in[6];
    const float *pin_w=(const float*)d_in[7], *pin_b=(const float*)d_in[8];
    const float *ln1_g=(const float*)d_in[9], *ln1_b=(const float*)d_in[10];
    const float *ln2_g=(const float*)d_in[11], *ln2_b=(const float*)d_in[12];
    const float *wq=(const float*)d_in[13], *wkv=(const float*)d_in[14], *wo=(const float*)d_in[15];
    const float *flg=(const float*)d_in[16], *flb=(const float*)d_in[17];
    const float *fw1=(const float*)d_in[18], *fw2=(const float*)d_in[19];
    const float *aw=(const float*)d_in[20], *ab=(const float*)d_in[21];
    const float *pout_w=(const float*)d_in[22], *pout_b=(const float*)d_in[23];
    const float *ng=(const float*)d_in[24], *nb=(const float*)d_in[25];
    float* out=(float*)d_out;

    cudaFuncSetAttribute(mgemm<CM_STORE>,cudaFuncAttributeMaxDynamicSharedMemorySize,SMB);
    cudaFuncSetAttribute(mgemm<CM_ATOM>, cudaFuncAttributeMaxDynamicSharedMemorySize,SMB);
    cudaFuncSetAttribute(mgemm<CM_SPLIT>,cudaFuncAttributeMaxDynamicSharedMemorySize,SMB);
    cudaFuncSetAttribute(mgemm32,cudaFuncAttributeMaxDynamicSharedMemorySize,2*SM32S);

    float *xp,*temb0,*temb1,*temb,*stemb,*ada,*lat,*q,*att,*vout,*hff,*h1;
    GSA(xp,g_xp); GSA(temb0,g_temb0); GSA(temb1,g_temb1); GSA(temb,g_temb);
    GSA(stemb,g_stemb); GSA(ada,g_ada); GSA(lat,g_lat); GSA(q,g_q);
    GSA(att,g_att); GSA(vout,g_vout); GSA(hff,g_hff); GSA(h1,g_h1);
    bf *inxH,*inxL,*pinH,*pinL,*xnH,*xnL,*xnTH,*xnTL,*latnH,*latnL,*qH,*qL,*qpH,*qpL;
    bf *attH,*attL,*ovH,*ovL,*voH,*voL,*hffH,*hffL,*h1H,*h1L,*latH,*latL,*stH,*stL;
    bf *wqH,*wqL,*kvH,*kvL,*kvTH,*kvTL,*woH,*woL,*f1H,*f1L,*f2H,*f2L,*awH,*awL,*poH,*poL;
    GSA(inxH,s_inxH); GSA(inxL,s_inxL); GSA(pinH,s_pinH); GSA(pinL,s_pinL);
    GSA(xnH,s_xnH); GSA(xnL,s_xnL); GSA(xnTH,s_xnTH); GSA(xnTL,s_xnTL);
    GSA(latnH,s_latnH); GSA(latnL,s_latnL); GSA(qH,s_qH); GSA(qL,s_qL);
    GSA(qpH,s_qpH); GSA(qpL,s_qpL); GSA(attH,s_attH); GSA(attL,s_attL);
    GSA(ovH,s_ovH); GSA(ovL,s_ovL); GSA(voH,s_voH); GSA(voL,s_voL);
    GSA(hffH,s_hffH); GSA(hffL,s_hffL); GSA(h1H,s_h1H); GSA(h1L,s_h1L);
    GSA(latH,s_latH); GSA(latL,s_latL); GSA(stH,s_stH); GSA(stL,s_stL);
    GSA(wqH,s_wqH); GSA(wqL,s_wqL); GSA(kvH,s_kvH); GSA(kvL,s_kvL);
    GSA(kvTH,s_kvTH); GSA(kvTL,s_kvTL); GSA(woH,s_woH); GSA(woL,s_woL);
    GSA(f1H,s_f1H); GSA(f1L,s_f1L); GSA(f2H,s_f2H); GSA(f2L,s_f2L);
    GSA(awH,s_awH); GSA(awL,s_awL); GSA(poH,s_poH); GSA(poL,s_poL);

    // launch 0..3: timestep chain (no prep deps)
    timestep_k<<<BS_,TD_>>>(in_ts,temb0);
    gemm_s<ACT_SILU><<<dim3(16,1),256>>>(BS_,D_,TD_,temb0,TD_,te_w1,D_,temb1,D_,te_b1);
    gemm_s<ACT_NONE><<<dim3(16,1),256>>>(BS_,D_,D_,temb1,D_,te_w2,D_,temb,D_,te_b2);
    silu_split_k<<<(BS_*D_+255)/256,256>>>(temb,stemb,stH,stL,BS_*D_);

    // launch 4: ALL prep in one kernel
    Segs S; int nbk=0; int si=0;
    auto addT=[&](const float* s, bf* h, bf* l, int K,int N,int z){
        S.src[si]=s;S.dh[si]=h;S.dl[si]=l;S.K[si]=K;S.N[si]=N;S.mode[si]=0;
        S.bstart[si]=nbk; nbk+=(N/32)*(K/32)*z; si++;
    };
    auto addS2=[&](const float* s, bf* h, bf* l, long n){
        S.src[si]=s;S.dh[si]=h;S.dl[si]=l;S.K[si]=(int)n;S.N[si]=1;S.mode[si]=1;
        S.bstart[si]=nbk; nbk+=(int)((n+2047)/2048); si++;
    };
    addT(pin_w,pinH,pinL,ED_,D_,1);
    addT(wq,wqH,wqL,D_,INNER,DEPTH);
    addT(wkv,kvTH,kvTL,D_,2*INNER,DEPTH);
    addT(wo,woH,woL,INNER,D_,DEPTH);
    addT(fw1,f1H,f1L,D_,FF_,DEPTH);
    addT(fw2,f2H,f2L,FF_,D_,DEPTH);
    addT(aw,awH,awL,D_,4*D_,DEPTH);
    addT(pout_w,poH,poL,D_,D_,1);
    addS2(wkv,kvH,kvL,(long)DEPTH*D_*2*INNER);
    addS2(in_x,inxH,inxL,(long)BS_*N1_*ED_);
    S.nseg=si; S.bstart[si]=nbk;
    prep_all<<<nbk,dim3(32,8)>>>(S);

    // launch 5: proj_in mgemm  (ncu -s 5 -c 1 profiles THIS)
    mgemm<CM_STORE><<<tg(BS_*N1_,D_,1),256,SMB>>>(
        BS_*N1_,D_,ED_,1, inxH,inxL,ED_,0, pinH,pinL,ED_,0,
        xp,NB_,NB_,D_,0, pin_b,nullptr,1.f);

    // batched adaLN for ALL layers (BM=32 tile)
    mgemm32<<<ADAW/128,256,2*SM32S>>>(ADAW,D_, stH,stL,D_, awH,awL,D_, ada,ADAW, ab);

    ln_k<false,true><<<BS_*N1_,256>>>(xp,nullptr,xnH,xnL,nullptr,nullptr);
    btransp<<<dim3(D_/32,N1_/32,BS_),dim3(32,8)>>>(xnH,xnL,xnTH,xnTL,N1_,D_);
    bcast_k<<<(BS_*NQ_*D_+255)/256,256>>>(in_lat,lat,BS_*NQ_*D_,NQ_*D_);

    for(int l=0;l<DEPTH;l++){
        const float *g1=ln1_g+l*D_, *b1=ln1_b+l*D_, *g2=ln2_g+l*D_, *b2=ln2_b+l*D_;
        const float *fg=flg+l*D_, *fb=flb+l*D_;
        const bf *wqh=wqH+(long)l*INNER*D_, *wql=wqL+(long)l*INNER*D_;
        const bf *kvh=kvH+(long)l*D_*2*INNER, *kvl=kvL+(long)l*D_*2*INNER;
        const bf *kvth=kvTH+(long)l*2*INNER*D_, *kvtl=kvTL+(long)l*2*INNER*D_;
        const bf *woh=woH+(long)l*D_*INNER, *wol=woL+(long)l*D_*INNER;
        const bf *f1h=f1H+(long)l*FF_*D_, *f1l=f1L+(long)l*FF_*D_;
        const bf *f2h=f2H+(long)l*D_*FF_, *f2l=f2L+(long)l*D_*FF_;

        cudaMemsetAsync(q,0,(size_t)BS_*NQ_*D_*sizeof(float),0);
        cudaMemsetAsync(vout,0,(size_t)BS_*NQ_*D_*sizeof(float),0);
        cudaMemsetAsync(h1,0,(size_t)BS_*NQ_*FF_*sizeof(float),0);

        // latn -> q (split-K=8) -> modulate+split
        ln_k<true,true><<<BS_*NQ_,256>>>(lat,nullptr,latnH,latnL,g2,b2);
        mgemm<CM_ATOM><<<tg(BS_*NQ_,INNER,8),256,SMB>>>(
            BS_*NQ_,INNER,D_,8, latnH,latnL,D_,0, wqh,wql,D_,0,
            q,NB_,NB_,INNER,0, nullptr,nullptr,1.f);
        modulate_k<<<(BS_*NQ_*D_+255)/256,256>>>(q,ada,l*4*D_,qH,qL);

        // qp(split out, ⊙g1) = SCALE * qmod_h @ wk_h^T (z=heads)
        mgemm<CM_SPLIT><<<tg(BS_*NQ_,D_,H_),256,SMB>>>(
            BS_*NQ_,D_,DH_,1, qH,qL,INNER,64, kvh,kvl,2*INNER,64,
            nullptr,qpH,qpL,H_*D_,(long)D_, nullptr,g1,SCALE_);

        // logits = qp' @ xn^T (z=batch); b1 drops (softmax shift-invariance)
        mgemm<CM_STORE><<<tg(NQ_*H_,N1_,BS_),256,SMB>>>(
            NQ_*H_,N1_,D_,1, qpH,qpL,D_,(long)NQ_*H_*D_, xnH,xnL,D_,(long)N1_*D_,
            att,NB_,NB_,N1_,(long)NQ_*H_*N1_, nullptr,nullptr,1.f);
        softmax_k<<<BS_*NQ_*H_,256>>>(att,attH,attL);

        // ov(split out, g1*x+b1) = attn @ xn (z=batch, via xnT)
        mgemm<CM_SPLIT><<<tg(NQ_*H_,D_,BS_),256,SMB>>>(
            NQ_*H_,D_,N1_,1, attH,attL,N1_,(long)NQ_*H_*N1_, xnTH,xnTL,N1_,(long)D_*N1_,
            nullptr,ovH,ovL,D_,(long)NQ_*H_*D_, b1,g1,1.f);

        // vout = ovm_h @ wv_h (z=heads, split-K=4)
        mgemm<CM_ATOM><<<tg(BS_*NQ_,DH_,H_*4),256,SMB>>>(
            BS_*NQ_,DH_,D_,4, ovH,ovL,H_*D_,(long)D_, kvth+(long)INNER*D_,kvtl+(long)INNER*D_,D_,(long)64*D_,
            vout,NB_,NB_,D_,64, nullptr,nullptr,1.f);
        split_k<<<(BS_*NQ_*D_+255)/256,256>>>(vout,voH,voL,BS_*NQ_*D_);

        // lat += vout @ wo (split-K=8)
        mgemm<CM_ATOM><<<tg(BS_*NQ_,D_,8),256,SMB>>>(
            BS_*NQ_,D_,INNER,8, voH,voL,INNER,0, woh,wol,INNER,0,
            lat,NB_,NB_,D_,0, nullptr,nullptr,1.f);

        // FF: h1 raw (split-K=2) -> GELU+split -> ff2 (split-K=8)
        ln_k<true,true><<<BS_*NQ_,256>>>(lat,nullptr,hffH,hffL,fg,fb);
        mgemm<CM_ATOM><<<tg(BS_*NQ_,FF_,2),256,SMB>>>(
            BS_*NQ_,FF_,D_,2, hffH,hffL,D_,0, f1h,f1l,D_,0,
            h1,NB_,NB_,FF_,0, nullptr,nullptr,1.f);
        gsplit_k<<<(BS_*NQ_*FF_+255)/256,256>>>(h1,h1H,h1L,BS_*NQ_*FF_);
        mgemm<CM_ATOM><<<tg(BS_*NQ_,D_,8),256,SMB>>>(
            BS_*NQ_,D_,FF_,8, h1H,h1L,FF_,0, f2h,f2l,FF_,0,
            lat,NB_,NB_,D_,0, nullptr,nullptr,1.f);
    }

    // ---- proj_out (split-K=8) + final LN ----
    split_k<<<(BS_*NQ_*D_+255)/256,256>>>(lat,latH,latL,BS_*NQ_*D_);
    cudaMemsetAsync(hff,0,(size_t)BS_*NQ_*D_*sizeof(float),0);
    mgemm<CM_ATOM><<<tg(BS_*NQ_,D_,8),256,SMB>>>(
        BS_*NQ_,D_,D_,8, latH,latL,D_,0, poH,poL,D_,0,
        hff,NB_,NB_,D_,0, pout_b,nullptr,1.f);
    ln_k<true,false><<<BS_*NQ_,256>>>(hff,out,nullptr,nullptr,ng,nb);
}